// round 1
// baseline (speedup 1.0000x reference)
#include <cuda_runtime.h>
#include <math.h>

#define D_ 512
#define B_ 16
#define LQ_ 1024
#define LK_ 1024
#define NROW_ (B_*LQ_)   // 16384

// ---------------- scratch (static device globals; no allocations) ----------
__device__ float g_vp[B_*LK_*D_];          // 33.5 MB
__device__ float g_scores[(long long)B_*LQ_*LK_];  // 67 MB (reused in-place for weights)
__device__ float g_fbw[B_*LQ_];
__device__ float g_attn[NROW_*D_];
__device__ float g_h1[NROW_*D_];
__device__ float g_h2[NROW_*(D_/2)];
__device__ float g_def[B_*D_];
__device__ float g_dh1[B_*D_];
__device__ float g_dh2[B_*(D_/2)];
__device__ unsigned g_umax;
__device__ unsigned g_umin;
__device__ float g_fb;
__device__ int g_maskmode;

// ---------------- ordered-uint float map for atomic min/max ----------------
__device__ __forceinline__ unsigned fmap(float f){
    unsigned u = __float_as_uint(f);
    return (u & 0x80000000u) ? ~u : (u | 0x80000000u);
}
__device__ __forceinline__ float funmap(unsigned m){
    return (m & 0x80000000u) ? __uint_as_float(m ^ 0x80000000u)
                             : __uint_as_float(~m);
}

// ---------------- init + mask dtype detection ------------------------------
// mask is logically bool[B,Lk]; on-wire could be u8 (1B), i32 (4B) or f32 (4B).
// Scan first 16384 bytes (safe for all encodings):
//   any byte > 1          -> f32 (0x80/0x3F bytes of 1.0f)       mode 2
//   any byte==1 at i%4!=0 -> u8  (dense 0/1 bytes)               mode 0
//   else                  -> i32 (value byte only at i%4==0)     mode 1
__global__ void k_init_detect(const unsigned char* __restrict__ mb){
    __shared__ int sGE2, sOff;
    int tid = threadIdx.x;
    if (tid == 0){ sGE2 = 0; sOff = 0; g_umax = 0u; g_umin = 0xFFFFFFFFu; }
    __syncthreads();
    int ge2 = 0, off = 0;
    for (int i = tid; i < B_*LK_; i += blockDim.x){
        unsigned char c = mb[i];
        if (c > 1) ge2 = 1;
        else if (c == 1 && (i & 3)) off = 1;
    }
    if (ge2) sGE2 = 1;
    if (off) sOff = 1;
    __syncthreads();
    if (tid == 0) g_maskmode = sGE2 ? 2 : (sOff ? 0 : 1);
}

// ---------------- generic NT SGEMM: C[m,n] = scale*sum_k A[m,k]*B[n,k] -----
// 128x128 tile, BK=8, 256 threads, 8x8 per-thread accumulators.
template<int ACT, bool BIAS, bool MINMAX>
__global__ void __launch_bounds__(256)
k_gemm_nt(const float* __restrict__ A, const float* __restrict__ Bm,
          const float* __restrict__ bias, float* __restrict__ C,
          int M, int N, int K,
          long long sA, long long sB, long long sC, float scale)
{
    __shared__ __align__(16) float As[8][128];
    __shared__ __align__(16) float Bs[8][128];
    __shared__ float red[512];

    const int bz = blockIdx.z;
    A  += (long long)bz * sA;
    Bm += (long long)bz * sB;
    C  += (long long)bz * sC;

    const int m0 = blockIdx.y * 128, n0 = blockIdx.x * 128;
    const int tid = threadIdx.x;
    const int tx = tid & 15, ty = tid >> 4;
    const int lrow = tid >> 1;          // 0..127
    const int lcol = (tid & 1) * 4;     // 0 or 4

    float acc[8][8];
    #pragma unroll
    for (int i = 0; i < 8; i++)
        #pragma unroll
        for (int j = 0; j < 8; j++) acc[i][j] = 0.f;

    for (int k0 = 0; k0 < K; k0 += 8){
        float4 av = make_float4(0.f,0.f,0.f,0.f);
        float4 bv = make_float4(0.f,0.f,0.f,0.f);
        if (m0 + lrow < M) av = *(const float4*)(A  + (long long)(m0+lrow)*K + (k0+lcol));
        if (n0 + lrow < N) bv = *(const float4*)(Bm + (long long)(n0+lrow)*K + (k0+lcol));
        As[lcol+0][lrow]=av.x; As[lcol+1][lrow]=av.y; As[lcol+2][lrow]=av.z; As[lcol+3][lrow]=av.w;
        Bs[lcol+0][lrow]=bv.x; Bs[lcol+1][lrow]=bv.y; Bs[lcol+2][lrow]=bv.z; Bs[lcol+3][lrow]=bv.w;
        __syncthreads();
        #pragma unroll
        for (int kk = 0; kk < 8; kk++){
            float4 a0 = *(const float4*)&As[kk][ty*8];
            float4 a1 = *(const float4*)&As[kk][ty*8+4];
            float4 b0 = *(const float4*)&Bs[kk][tx*8];
            float4 b1 = *(const float4*)&Bs[kk][tx*8+4];
            float a[8] = {a0.x,a0.y,a0.z,a0.w,a1.x,a1.y,a1.z,a1.w};
            float b[8] = {b0.x,b0.y,b0.z,b0.w,b1.x,b1.y,b1.z,b1.w};
            #pragma unroll
            for (int i = 0; i < 8; i++)
                #pragma unroll
                for (int j = 0; j < 8; j++)
                    acc[i][j] = fmaf(a[i], b[j], acc[i][j]);
        }
        __syncthreads();
    }

    float lmax = -INFINITY, lmin = INFINITY;
    #pragma unroll
    for (int i = 0; i < 8; i++){
        int m = m0 + ty*8 + i;
        if (m < M){
            #pragma unroll
            for (int j = 0; j < 8; j++){
                int n = n0 + tx*8 + j;
                if (n < N){
                    float v = acc[i][j] * scale;
                    if (BIAS) v += bias[n];
                    if (ACT == 1) v = fmaxf(v, 0.f);
                    C[(long long)m * N + n] = v;
                    if (MINMAX){ lmax = fmaxf(lmax, v); lmin = fminf(lmin, v); }
                }
            }
        }
    }
    if (MINMAX){
        red[tid] = lmax; red[256+tid] = lmin;
        __syncthreads();
        for (int st = 128; st > 0; st >>= 1){
            if (tid < st){
                red[tid]     = fmaxf(red[tid],     red[tid+st]);
                red[256+tid] = fminf(red[256+tid], red[256+tid+st]);
            }
            __syncthreads();
        }
        if (tid == 0){
            atomicMax(&g_umax, fmap(red[0]));
            atomicMin(&g_umin, fmap(red[256]));
        }
    }
}

// ---------------- fallback-score EMA ---------------------------------------
__global__ void k_fb(const float* __restrict__ fallback){
    if (threadIdx.x == 0){
        float bmax = funmap(g_umax), bmin = funmap(g_umin);
        const float M_ = 0.99f;
        g_fb = M_ * fallback[0] + (1.0f - M_) * ((bmax + bmin) * 0.5f);
    }
}

// ---------------- row softmax (in place), appended fallback column ---------
__global__ void __launch_bounds__(256)
k_softmax(float* __restrict__ scores, float* __restrict__ fbw,
          const void* __restrict__ maskp)
{
    __shared__ float red[256];
    const int row = blockIdx.x;           // 0..16383
    const int b = row >> 10;              // Lq = 1024
    const int tid = threadIdx.x;
    float* s = scores + (long long)row * LK_;
    const int mode = g_maskmode;
    const float fb = g_fb;

    float4 v = ((const float4*)s)[tid];
    float x[4] = {v.x, v.y, v.z, v.w};
    int mk[4];
    const int base = b * LK_ + tid * 4;   // multiple of 4
    if (mode == 0){
        uchar4 m4 = ((const uchar4*)maskp)[base >> 2];
        mk[0]=m4.x!=0; mk[1]=m4.y!=0; mk[2]=m4.z!=0; mk[3]=m4.w!=0;
    } else if (mode == 1){
        int4 m4 = ((const int4*)maskp)[base >> 2];
        mk[0]=m4.x!=0; mk[1]=m4.y!=0; mk[2]=m4.z!=0; mk[3]=m4.w!=0;
    } else {
        float4 m4 = ((const float4*)maskp)[base >> 2];
        mk[0]=m4.x!=0.f; mk[1]=m4.y!=0.f; mk[2]=m4.z!=0.f; mk[3]=m4.w!=0.f;
    }

    float lmax = fb;
    #pragma unroll
    for (int c = 0; c < 4; c++) if (!mk[c]) lmax = fmaxf(lmax, x[c]);
    red[tid] = lmax; __syncthreads();
    for (int st = 128; st > 0; st >>= 1){
        if (tid < st) red[tid] = fmaxf(red[tid], red[tid+st]);
        __syncthreads();
    }
    const float m = red[0];
    __syncthreads();

    float e[4]; float lsum = 0.f;
    #pragma unroll
    for (int c = 0; c < 4; c++){
        e[c] = mk[c] ? 0.f : expf(x[c] - m);
        lsum += e[c];
    }
    red[tid] = lsum; __syncthreads();
    for (int st = 128; st > 0; st >>= 1){
        if (tid < st) red[tid] += red[tid+st];
        __syncthreads();
    }
    const float fbe = expf(fb - m);
    const float inv = 1.f / (red[0] + fbe);
    ((float4*)s)[tid] = make_float4(e[0]*inv, e[1]*inv, e[2]*inv, e[3]*inv);
    if (tid == 0) fbw[row] = fbe * inv;
}

// ---------------- NN GEMM: out = weights @ v_p + fbw * defaults ------------
__global__ void __launch_bounds__(256)
k_gemm_nn_attn(const float* __restrict__ A, const float* __restrict__ Bm,
               float* __restrict__ C, int M, int N, int K,
               long long sA, long long sB, long long sC,
               const float* __restrict__ fbw, const float* __restrict__ defv)
{
    __shared__ __align__(16) float As[8][128];
    __shared__ __align__(16) float Bs[8][128];

    const int bz = blockIdx.z;
    A  += (long long)bz * sA;
    Bm += (long long)bz * sB;
    C  += (long long)bz * sC;

    const int m0 = blockIdx.y * 128, n0 = blockIdx.x * 128;
    const int tid = threadIdx.x;
    const int tx = tid & 15, ty = tid >> 4;
    const int lrow = tid >> 1;
    const int lcol = (tid & 1) * 4;
    const int bk = tid >> 5;            // 0..7
    const int bn4 = (tid & 31) * 4;     // 0..124

    float acc[8][8];
    #pragma unroll
    for (int i = 0; i < 8; i++)
        #pragma unroll
        for (int j = 0; j < 8; j++) acc[i][j] = 0.f;

    for (int k0 = 0; k0 < K; k0 += 8){
        float4 av = make_float4(0.f,0.f,0.f,0.f);
        float4 bv = make_float4(0.f,0.f,0.f,0.f);
        if (m0 + lrow < M) av = *(const float4*)(A  + (long long)(m0+lrow)*K + (k0+lcol));
        if (n0 + bn4  < N) bv = *(const float4*)(Bm + (long long)(k0+bk)*N + (n0+bn4));
        As[lcol+0][lrow]=av.x; As[lcol+1][lrow]=av.y; As[lcol+2][lrow]=av.z; As[lcol+3][lrow]=av.w;
        *(float4*)&Bs[bk][bn4] = bv;
        __syncthreads();
        #pragma unroll
        for (int kk = 0; kk < 8; kk++){
            float4 a0 = *(const float4*)&As[kk][ty*8];
            float4 a1 = *(const float4*)&As[kk][ty*8+4];
            float4 b0 = *(const float4*)&Bs[kk][tx*8];
            float4 b1 = *(const float4*)&Bs[kk][tx*8+4];
            float a[8] = {a0.x,a0.y,a0.z,a0.w,a1.x,a1.y,a1.z,a1.w};
            float b[8] = {b0.x,b0.y,b0.z,b0.w,b1.x,b1.y,b1.z,b1.w};
            #pragma unroll
            for (int i = 0; i < 8; i++)
                #pragma unroll
                for (int j = 0; j < 8; j++)
                    acc[i][j] = fmaf(a[i], b[j], acc[i][j]);
        }
        __syncthreads();
    }

    #pragma unroll
    for (int i = 0; i < 8; i++){
        int m = m0 + ty*8 + i;
        if (m < M){
            float fw = fbw[bz * LQ_ + m];
            #pragma unroll
            for (int j = 0; j < 8; j++){
                int n = n0 + tx*8 + j;
                if (n < N)
                    C[(long long)m * N + n] = acc[i][j] + fw * defv[bz * D_ + n];
            }
        }
    }
}

// ---------------- final scorer layer: tanh(h2 @ W3^T + b3) -----------------
__global__ void k_scorer3(const float* __restrict__ H2, const float* __restrict__ W3,
                          const float* __restrict__ b3, float* __restrict__ out, int M)
{
    int warp = threadIdx.x >> 5, lane = threadIdx.x & 31;
    int row = blockIdx.x * 8 + warp;
    if (row >= M) return;
    const float* h = H2 + (long long)row * (D_/2);
    float sum = 0.f;
    #pragma unroll
    for (int t = 0; t < 8; t++){
        int j = lane + t*32;
        sum = fmaf(h[j], W3[j], sum);
    }
    #pragma unroll
    for (int o = 16; o > 0; o >>= 1) sum += __shfl_down_sync(0xffffffffu, sum, o);
    if (lane == 0) out[row] = tanhf(sum + b3[0]);
}

// ---------------------------------------------------------------------------
extern "C" void kernel_launch(void* const* d_in, const int* in_sizes, int n_in,
                              void* d_out, int out_size)
{
    const float* uncond_q = (const float*)d_in[0];
    const float* q        = (const float*)d_in[1];
    const float* k        = (const float*)d_in[2];
    const float* v        = (const float*)d_in[3];
    const void*  mask     = d_in[4];
    const float* fallback = (const float*)d_in[5];
    const float* Wv = (const float*)d_in[6];
    const float* bv = (const float*)d_in[7];
    const float* Wf = (const float*)d_in[8];
    const float* bf = (const float*)d_in[9];
    const float* W1 = (const float*)d_in[10];
    const float* b1 = (const float*)d_in[11];
    const float* W2 = (const float*)d_in[12];
    const float* b2 = (const float*)d_in[13];
    const float* W3 = (const float*)d_in[14];
    const float* b3 = (const float*)d_in[15];

    float *vp, *scores, *fbw, *attn, *h1, *h2, *defv, *dh1, *dh2;
    cudaGetSymbolAddress((void**)&vp,     g_vp);
    cudaGetSymbolAddress((void**)&scores, g_scores);
    cudaGetSymbolAddress((void**)&fbw,    g_fbw);
    cudaGetSymbolAddress((void**)&attn,   g_attn);
    cudaGetSymbolAddress((void**)&h1,     g_h1);
    cudaGetSymbolAddress((void**)&h2,     g_h2);
    cudaGetSymbolAddress((void**)&defv,   g_def);
    cudaGetSymbolAddress((void**)&dh1,    g_dh1);
    cudaGetSymbolAddress((void**)&dh2,    g_dh2);

    const float inv_sqrt_d = 0.04419417382415922f; // 1/sqrt(512)
    const long long sQ = (long long)LQ_ * D_;
    const long long sK = (long long)LK_ * D_;
    const long long sS = (long long)LQ_ * LK_;

    // 0) init min/max + detect mask dtype
    k_init_detect<<<1, 256>>>((const unsigned char*)mask);

    // 1) v_p = V @ Wv^T + bv   [16384, 512]
    k_gemm_nt<0, true, false><<<dim3(4,128,1), 256>>>(v, Wv, bv, vp,
        NROW_, D_, D_, 0, 0, 0, 1.f);

    // 2) defaults = uncond_q @ Wf^T + bf   [16, 512]
    k_gemm_nt<0, true, false><<<dim3(4,1,1), 256>>>(uncond_q, Wf, bf, defv,
        B_, D_, D_, 0, 0, 0, 1.f);

    // 3) scores = Q @ K^T / sqrt(D)  per batch, with global min/max reduction
    k_gemm_nt<0, false, true><<<dim3(8,8,B_), 256>>>(q, k, nullptr, scores,
        LQ_, LK_, D_, sQ, sK, sS, inv_sqrt_d);

    // 4) fb = EMA(fallback, (max+min)/2)
    k_fb<<<1, 32>>>(fallback);

    // 5) masked softmax over [scores, fb] per row; weights in place + fbw
    k_softmax<<<NROW_, 256>>>(scores, fbw, mask);

    // 6) out = weights @ v_p + fbw * defaults   [per batch 1024x512]
    k_gemm_nn_attn<<<dim3(4,8,B_), 256>>>(scores, vp, attn,
        LQ_, D_, LK_, sS, sK, sQ, fbw, defv);

    // 7) scorer on out
    k_gemm_nt<1, true, false><<<dim3(4,128,1), 256>>>(attn, W1, b1, h1,
        NROW_, D_, D_, 0, 0, 0, 1.f);
    k_gemm_nt<1, true, false><<<dim3(2,128,1), 256>>>(h1, W2, b2, h2,
        NROW_, D_/2, D_, 0, 0, 0, 1.f);

    // 8) scorer on defaults
    k_gemm_nt<1, true, false><<<dim3(4,1,1), 256>>>(defv, W1, b1, dh1,
        B_, D_, D_, 0, 0, 0, 1.f);
    k_gemm_nt<1, true, false><<<dim3(2,1,1), 256>>>(dh1, W2, b2, dh2,
        B_, D_/2, D_, 0, 0, 0, 1.f);

    // 9) final tanh layers -> outputs (main [16384], defaults [16])
    float* out = (float*)d_out;
    k_scorer3<<<NROW_/8, 256>>>(h2, W3, b3, out, NROW_);
    if (out_size >= NROW_ + B_)
        k_scorer3<<<2, 256>>>(dh2, W3, b3, out + NROW_, B_);
}

// round 2
// speedup vs baseline: 2.0718x; 2.0718x over previous
#include <cuda_runtime.h>
#include <math.h>

#define D_ 512
#define B_ 16
#define LQ_ 1024
#define LK_ 1024
#define NROW_ (B_*LQ_)   // 16384

// ---------------- scratch (static device globals; no allocations) ----------
__device__ float g_vp[B_*LK_*D_];                  // 33.5 MB
__device__ float g_scores[(long long)B_*LQ_*LK_];  // 67 MB (reused in-place for weights)
__device__ float g_fbw[B_*LQ_];
__device__ float g_attn[NROW_*D_];
__device__ float g_h1[NROW_*D_];
__device__ float g_h2[NROW_*(D_/2)];
__device__ float g_def[B_*D_];
__device__ float g_dh1[B_*D_];
__device__ float g_dh2[B_*(D_/2)];
__device__ unsigned g_umax;
__device__ unsigned g_umin;
__device__ float g_fb;
__device__ int g_maskmode;

// ---------------- ordered-uint float map for atomic min/max ----------------
__device__ __forceinline__ unsigned fmap(float f){
    unsigned u = __float_as_uint(f);
    return (u & 0x80000000u) ? ~u : (u | 0x80000000u);
}
__device__ __forceinline__ float funmap(unsigned m){
    return (m & 0x80000000u) ? __uint_as_float(m ^ 0x80000000u)
                             : __uint_as_float(~m);
}

#define TFCVT(d,s) asm("cvt.rna.tf32.f32 %0, %1;" : "=r"(d) : "f"(s))

// ---------------- init + mask dtype detection ------------------------------
__global__ void k_init_detect(const unsigned char* __restrict__ mb){
    __shared__ int sGE2, sOff;
    int tid = threadIdx.x;
    if (tid == 0){ sGE2 = 0; sOff = 0; g_umax = 0u; g_umin = 0xFFFFFFFFu; }
    __syncthreads();
    int ge2 = 0, off = 0;
    for (int i = tid; i < B_*LK_; i += blockDim.x){
        unsigned char c = mb[i];
        if (c > 1) ge2 = 1;
        else if (c == 1 && (i & 3)) off = 1;
    }
    if (ge2) sGE2 = 1;
    if (off) sOff = 1;
    __syncthreads();
    if (tid == 0) g_maskmode = sGE2 ? 2 : (sOff ? 0 : 1);
}

// =================== tensor-core tf32 NT GEMM ==============================
// C[m,n] = scale * sum_k A[m,k]*B[n,k]  (+bias, +relu, +global minmax)
// 128x128 tile, BK=32, 8 warps (4x2), warp tile 32x64 via m16n8k8 tf32 mma.
// Requires: M,N multiples of 128, K multiple of 32.
template<int ACT, bool BIAS, bool MINMAX>
__global__ void __launch_bounds__(256)
k_tc_nt(const float* __restrict__ A, const float* __restrict__ Bm,
        const float* __restrict__ bias, float* __restrict__ C,
        int N, int K, long long sA, long long sB, long long sC, float scale)
{
    __shared__ unsigned As[32][136];
    __shared__ unsigned Bs[32][136];
    __shared__ float red[512];

    const int bz = blockIdx.z;
    A  += (long long)bz * sA;
    Bm += (long long)bz * sB;
    C  += (long long)bz * sC;

    const int m0 = blockIdx.y * 128, n0 = blockIdx.x * 128;
    const int tid = threadIdx.x;
    const int lane = tid & 31, warp = tid >> 5;
    const int rbase = (warp & 3) * 32;      // warp row base in tile
    const int cbase = (warp >> 2) * 64;     // warp col base in tile
    const int grp = lane >> 2, qd = lane & 3;

    const int lr = tid >> 1;                // 0..127 (row for global load)
    const int lc = (tid & 1) * 16;          // 0 or 16 (k-col base)

    const float* Aptr = A + (long long)(m0 + lr) * K + lc;
    const float* Bptr = Bm + (long long)(n0 + lr) * K + lc;

    float acc[2][8][4];
    #pragma unroll
    for (int t = 0; t < 2; t++)
        #pragma unroll
        for (int u = 0; u < 8; u++)
            #pragma unroll
            for (int r = 0; r < 4; r++) acc[t][u][r] = 0.f;

    for (int k0 = 0; k0 < K; k0 += 32){
        float4 av[4], bv[4];
        #pragma unroll
        for (int i = 0; i < 4; i++){
            av[i] = *(const float4*)(Aptr + k0 + i*4);
            bv[i] = *(const float4*)(Bptr + k0 + i*4);
        }
        __syncthreads();
        #pragma unroll
        for (int i = 0; i < 4; i++){
            unsigned t0,t1,t2,t3;
            TFCVT(t0, av[i].x); TFCVT(t1, av[i].y); TFCVT(t2, av[i].z); TFCVT(t3, av[i].w);
            As[lc+i*4+0][lr]=t0; As[lc+i*4+1][lr]=t1; As[lc+i*4+2][lr]=t2; As[lc+i*4+3][lr]=t3;
            TFCVT(t0, bv[i].x); TFCVT(t1, bv[i].y); TFCVT(t2, bv[i].z); TFCVT(t3, bv[i].w);
            Bs[lc+i*4+0][lr]=t0; Bs[lc+i*4+1][lr]=t1; Bs[lc+i*4+2][lr]=t2; Bs[lc+i*4+3][lr]=t3;
        }
        __syncthreads();
        #pragma unroll
        for (int kk = 0; kk < 32; kk += 8){
            unsigned a[2][4], b[8][2];
            #pragma unroll
            for (int t = 0; t < 2; t++){
                int m = rbase + t*16 + grp;
                a[t][0] = As[kk+qd  ][m];
                a[t][1] = As[kk+qd  ][m+8];
                a[t][2] = As[kk+qd+4][m];
                a[t][3] = As[kk+qd+4][m+8];
            }
            #pragma unroll
            for (int u = 0; u < 8; u++){
                int n = cbase + u*8 + grp;
                b[u][0] = Bs[kk+qd  ][n];
                b[u][1] = Bs[kk+qd+4][n];
            }
            #pragma unroll
            for (int t = 0; t < 2; t++)
                #pragma unroll
                for (int u = 0; u < 8; u++){
                    asm volatile(
                        "mma.sync.aligned.m16n8k8.row.col.f32.tf32.tf32.f32 "
                        "{%0,%1,%2,%3}, {%4,%5,%6,%7}, {%8,%9}, {%0,%1,%2,%3};"
                        : "+f"(acc[t][u][0]), "+f"(acc[t][u][1]),
                          "+f"(acc[t][u][2]), "+f"(acc[t][u][3])
                        : "r"(a[t][0]), "r"(a[t][1]), "r"(a[t][2]), "r"(a[t][3]),
                          "r"(b[u][0]), "r"(b[u][1]));
                }
        }
    }

    float lmax = -INFINITY, lmin = INFINITY;
    #pragma unroll
    for (int t = 0; t < 2; t++){
        #pragma unroll
        for (int u = 0; u < 8; u++){
            int row = m0 + rbase + t*16 + grp;
            int col = n0 + cbase + u*8 + qd*2;
            float v0 = acc[t][u][0]*scale, v1 = acc[t][u][1]*scale;
            float v2 = acc[t][u][2]*scale, v3 = acc[t][u][3]*scale;
            if (BIAS){
                float b0 = bias[col], b1 = bias[col+1];
                v0 += b0; v1 += b1; v2 += b0; v3 += b1;
            }
            if (ACT == 1){
                v0 = fmaxf(v0,0.f); v1 = fmaxf(v1,0.f);
                v2 = fmaxf(v2,0.f); v3 = fmaxf(v3,0.f);
            }
            *(float2*)(C + (long long)row*N + col)     = make_float2(v0, v1);
            *(float2*)(C + (long long)(row+8)*N + col) = make_float2(v2, v3);
            if (MINMAX){
                lmax = fmaxf(fmaxf(lmax, fmaxf(v0,v1)), fmaxf(v2,v3));
                lmin = fminf(fminf(lmin, fminf(v0,v1)), fminf(v2,v3));
            }
        }
    }
    if (MINMAX){
        red[tid] = lmax; red[256+tid] = lmin;
        __syncthreads();
        for (int st = 128; st > 0; st >>= 1){
            if (tid < st){
                red[tid]     = fmaxf(red[tid],     red[tid+st]);
                red[256+tid] = fminf(red[256+tid], red[256+tid+st]);
            }
            __syncthreads();
        }
        if (tid == 0){
            atomicMax(&g_umax, fmap(red[0]));
            atomicMin(&g_umin, fmap(red[256]));
        }
    }
}

// =================== tensor-core tf32 NN GEMM (attention output) ===========
// C[m,n] = sum_k A[m,k]*B[k,n] + fbw[m]*defv[n]; A row-major, B row-major.
__global__ void __launch_bounds__(256)
k_tc_nn_attn(const float* __restrict__ A, const float* __restrict__ Bm,
             float* __restrict__ C, int N, int K,
             long long sA, long long sB, long long sC,
             const float* __restrict__ fbw, const float* __restrict__ defv)
{
    __shared__ unsigned As[32][136];
    __shared__ unsigned Bs[32][136];

    const int bz = blockIdx.z;
    A  += (long long)bz * sA;
    Bm += (long long)bz * sB;
    C  += (long long)bz * sC;

    const int m0 = blockIdx.y * 128, n0 = blockIdx.x * 128;
    const int tid = threadIdx.x;
    const int lane = tid & 31, warp = tid >> 5;
    const int rbase = (warp & 3) * 32;
    const int cbase = (warp >> 2) * 64;
    const int grp = lane >> 2, qd = lane & 3;

    const int lr = tid >> 1;            // A load row
    const int lc = (tid & 1) * 16;      // A load k base
    const int bkr = tid >> 3;           // B load k row 0..31
    const int bnc = (tid & 7) * 16;     // B load n base

    const float* Aptr = A + (long long)(m0 + lr) * K + lc;
    const float* Bptr = Bm + (long long)bkr * N + n0 + bnc;

    float acc[2][8][4];
    #pragma unroll
    for (int t = 0; t < 2; t++)
        #pragma unroll
        for (int u = 0; u < 8; u++)
            #pragma unroll
            for (int r = 0; r < 4; r++) acc[t][u][r] = 0.f;

    for (int k0 = 0; k0 < K; k0 += 32){
        float4 av[4], bv[4];
        #pragma unroll
        for (int i = 0; i < 4; i++){
            av[i] = *(const float4*)(Aptr + k0 + i*4);
            bv[i] = *(const float4*)(Bptr + (long long)k0 * N + i*4);
        }
        __syncthreads();
        #pragma unroll
        for (int i = 0; i < 4; i++){
            unsigned t0,t1,t2,t3;
            TFCVT(t0, av[i].x); TFCVT(t1, av[i].y); TFCVT(t2, av[i].z); TFCVT(t3, av[i].w);
            As[lc+i*4+0][lr]=t0; As[lc+i*4+1][lr]=t1; As[lc+i*4+2][lr]=t2; As[lc+i*4+3][lr]=t3;
            TFCVT(t0, bv[i].x); TFCVT(t1, bv[i].y); TFCVT(t2, bv[i].z); TFCVT(t3, bv[i].w);
            Bs[bkr][bnc+i*4+0]=t0; Bs[bkr][bnc+i*4+1]=t1; Bs[bkr][bnc+i*4+2]=t2; Bs[bkr][bnc+i*4+3]=t3;
        }
        __syncthreads();
        #pragma unroll
        for (int kk = 0; kk < 32; kk += 8){
            unsigned a[2][4], b[8][2];
            #pragma unroll
            for (int t = 0; t < 2; t++){
                int m = rbase + t*16 + grp;
                a[t][0] = As[kk+qd  ][m];
                a[t][1] = As[kk+qd  ][m+8];
                a[t][2] = As[kk+qd+4][m];
                a[t][3] = As[kk+qd+4][m+8];
            }
            #pragma unroll
            for (int u = 0; u < 8; u++){
                int n = cbase + u*8 + grp;
                b[u][0] = Bs[kk+qd  ][n];
                b[u][1] = Bs[kk+qd+4][n];
            }
            #pragma unroll
            for (int t = 0; t < 2; t++)
                #pragma unroll
                for (int u = 0; u < 8; u++){
                    asm volatile(
                        "mma.sync.aligned.m16n8k8.row.col.f32.tf32.tf32.f32 "
                        "{%0,%1,%2,%3}, {%4,%5,%6,%7}, {%8,%9}, {%0,%1,%2,%3};"
                        : "+f"(acc[t][u][0]), "+f"(acc[t][u][1]),
                          "+f"(acc[t][u][2]), "+f"(acc[t][u][3])
                        : "r"(a[t][0]), "r"(a[t][1]), "r"(a[t][2]), "r"(a[t][3]),
                          "r"(b[u][0]), "r"(b[u][1]));
                }
        }
    }

    #pragma unroll
    for (int t = 0; t < 2; t++){
        int row = m0 + rbase + t*16 + grp;
        float fw0 = fbw[bz*LQ_ + row], fw1 = fbw[bz*LQ_ + row + 8];
        #pragma unroll
        for (int u = 0; u < 8; u++){
            int col = n0 + cbase + u*8 + qd*2;
            float d0 = defv[bz*D_ + col], d1 = defv[bz*D_ + col + 1];
            *(float2*)(C + (long long)row*N + col) =
                make_float2(acc[t][u][0] + fw0*d0, acc[t][u][1] + fw0*d1);
            *(float2*)(C + (long long)(row+8)*N + col) =
                make_float2(acc[t][u][2] + fw1*d0, acc[t][u][3] + fw1*d1);
        }
    }
}

// ---------------- legacy SIMT NT GEMM (for tiny M=16 GEMMs) ----------------
template<int ACT, bool BIAS>
__global__ void __launch_bounds__(256)
k_gemm_nt(const float* __restrict__ A, const float* __restrict__ Bm,
          const float* __restrict__ bias, float* __restrict__ C,
          int M, int N, int K, float scale)
{
    __shared__ __align__(16) float As[8][128];
    __shared__ __align__(16) float Bs[8][128];

    const int m0 = blockIdx.y * 128, n0 = blockIdx.x * 128;
    const int tid = threadIdx.x;
    const int tx = tid & 15, ty = tid >> 4;
    const int lrow = tid >> 1;
    const int lcol = (tid & 1) * 4;

    float acc[8][8];
    #pragma unroll
    for (int i = 0; i < 8; i++)
        #pragma unroll
        for (int j = 0; j < 8; j++) acc[i][j] = 0.f;

    for (int k0 = 0; k0 < K; k0 += 8){
        float4 av = make_float4(0.f,0.f,0.f,0.f);
        float4 bv = make_float4(0.f,0.f,0.f,0.f);
        if (m0 + lrow < M) av = *(const float4*)(A  + (long long)(m0+lrow)*K + (k0+lcol));
        if (n0 + lrow < N) bv = *(const float4*)(Bm + (long long)(n0+lrow)*K + (k0+lcol));
        As[lcol+0][lrow]=av.x; As[lcol+1][lrow]=av.y; As[lcol+2][lrow]=av.z; As[lcol+3][lrow]=av.w;
        Bs[lcol+0][lrow]=bv.x; Bs[lcol+1][lrow]=bv.y; Bs[lcol+2][lrow]=bv.z; Bs[lcol+3][lrow]=bv.w;
        __syncthreads();
        #pragma unroll
        for (int kk = 0; kk < 8; kk++){
            float4 a0 = *(const float4*)&As[kk][ty*8];
            float4 a1 = *(const float4*)&As[kk][ty*8+4];
            float4 b0 = *(const float4*)&Bs[kk][tx*8];
            float4 b1 = *(const float4*)&Bs[kk][tx*8+4];
            float a[8] = {a0.x,a0.y,a0.z,a0.w,a1.x,a1.y,a1.z,a1.w};
            float b[8] = {b0.x,b0.y,b0.z,b0.w,b1.x,b1.y,b1.z,b1.w};
            #pragma unroll
            for (int i = 0; i < 8; i++)
                #pragma unroll
                for (int j = 0; j < 8; j++)
                    acc[i][j] = fmaf(a[i], b[j], acc[i][j]);
        }
        __syncthreads();
    }

    #pragma unroll
    for (int i = 0; i < 8; i++){
        int m = m0 + ty*8 + i;
        if (m < M){
            #pragma unroll
            for (int j = 0; j < 8; j++){
                int n = n0 + tx*8 + j;
                if (n < N){
                    float v = acc[i][j] * scale;
                    if (BIAS) v += bias[n];
                    if (ACT == 1) v = fmaxf(v, 0.f);
                    C[(long long)m * N + n] = v;
                }
            }
        }
    }
}

// ---------------- fallback-score EMA ---------------------------------------
__global__ void k_fb(const float* __restrict__ fallback){
    if (threadIdx.x == 0){
        float bmax = funmap(g_umax), bmin = funmap(g_umin);
        const float M_ = 0.99f;
        g_fb = M_ * fallback[0] + (1.0f - M_) * ((bmax + bmin) * 0.5f);
    }
}

// ---------------- row softmax (in place), appended fallback column ---------
__global__ void __launch_bounds__(256)
k_softmax(float* __restrict__ scores, float* __restrict__ fbw,
          const void* __restrict__ maskp)
{
    __shared__ float red[256];
    const int row = blockIdx.x;
    const int b = row >> 10;
    const int tid = threadIdx.x;
    float* s = scores + (long long)row * LK_;
    const int mode = g_maskmode;
    const float fb = g_fb;

    float4 v = ((const float4*)s)[tid];
    float x[4] = {v.x, v.y, v.z, v.w};
    int mk[4];
    const int base = b * LK_ + tid * 4;
    if (mode == 0){
        uchar4 m4 = ((const uchar4*)maskp)[base >> 2];
        mk[0]=m4.x!=0; mk[1]=m4.y!=0; mk[2]=m4.z!=0; mk[3]=m4.w!=0;
    } else if (mode == 1){
        int4 m4 = ((const int4*)maskp)[base >> 2];
        mk[0]=m4.x!=0; mk[1]=m4.y!=0; mk[2]=m4.z!=0; mk[3]=m4.w!=0;
    } else {
        float4 m4 = ((const float4*)maskp)[base >> 2];
        mk[0]=m4.x!=0.f; mk[1]=m4.y!=0.f; mk[2]=m4.z!=0.f; mk[3]=m4.w!=0.f;
    }

    float lmax = fb;
    #pragma unroll
    for (int c = 0; c < 4; c++) if (!mk[c]) lmax = fmaxf(lmax, x[c]);
    red[tid] = lmax; __syncthreads();
    for (int st = 128; st > 0; st >>= 1){
        if (tid < st) red[tid] = fmaxf(red[tid], red[tid+st]);
        __syncthreads();
    }
    const float m = red[0];
    __syncthreads();

    float e[4]; float lsum = 0.f;
    #pragma unroll
    for (int c = 0; c < 4; c++){
        e[c] = mk[c] ? 0.f : expf(x[c] - m);
        lsum += e[c];
    }
    red[tid] = lsum; __syncthreads();
    for (int st = 128; st > 0; st >>= 1){
        if (tid < st) red[tid] += red[tid+st];
        __syncthreads();
    }
    const float fbe = expf(fb - m);
    const float inv = 1.f / (red[0] + fbe);
    ((float4*)s)[tid] = make_float4(e[0]*inv, e[1]*inv, e[2]*inv, e[3]*inv);
    if (tid == 0) fbw[row] = fbe * inv;
}

// ---------------- final scorer layer: tanh(h2 @ W3^T + b3) -----------------
__global__ void k_scorer3(const float* __restrict__ H2, const float* __restrict__ W3,
                          const float* __restrict__ b3, float* __restrict__ out, int M)
{
    int warp = threadIdx.x >> 5, lane = threadIdx.x & 31;
    int row = blockIdx.x * 8 + warp;
    if (row >= M) return;
    const float* h = H2 + (long long)row * (D_/2);
    float sum = 0.f;
    #pragma unroll
    for (int t = 0; t < 8; t++){
        int j = lane + t*32;
        sum = fmaf(h[j], W3[j], sum);
    }
    #pragma unroll
    for (int o = 16; o > 0; o >>= 1) sum += __shfl_down_sync(0xffffffffu, sum, o);
    if (lane == 0) out[row] = tanhf(sum + b3[0]);
}

// ---------------------------------------------------------------------------
extern "C" void kernel_launch(void* const* d_in, const int* in_sizes, int n_in,
                              void* d_out, int out_size)
{
    const float* uncond_q = (const float*)d_in[0];
    const float* q        = (const float*)d_in[1];
    const float* k        = (const float*)d_in[2];
    const float* v        = (const float*)d_in[3];
    const void*  mask     = d_in[4];
    const float* fallback = (const float*)d_in[5];
    const float* Wv = (const float*)d_in[6];
    const float* bv = (const float*)d_in[7];
    const float* Wf = (const float*)d_in[8];
    const float* bf = (const float*)d_in[9];
    const float* W1 = (const float*)d_in[10];
    const float* b1 = (const float*)d_in[11];
    const float* W2 = (const float*)d_in[12];
    const float* b2 = (const float*)d_in[13];
    const float* W3 = (const float*)d_in[14];
    const float* b3 = (const float*)d_in[15];

    float *vp, *scores, *fbw, *attn, *h1, *h2, *defv, *dh1, *dh2;
    cudaGetSymbolAddress((void**)&vp,     g_vp);
    cudaGetSymbolAddress((void**)&scores, g_scores);
    cudaGetSymbolAddress((void**)&fbw,    g_fbw);
    cudaGetSymbolAddress((void**)&attn,   g_attn);
    cudaGetSymbolAddress((void**)&h1,     g_h1);
    cudaGetSymbolAddress((void**)&h2,     g_h2);
    cudaGetSymbolAddress((void**)&defv,   g_def);
    cudaGetSymbolAddress((void**)&dh1,    g_dh1);
    cudaGetSymbolAddress((void**)&dh2,    g_dh2);

    const float inv_sqrt_d = 0.04419417382415922f; // 1/sqrt(512)
    const long long sQ = (long long)LQ_ * D_;
    const long long sK = (long long)LK_ * D_;
    const long long sS = (long long)LQ_ * LK_;

    // 0) init min/max + detect mask dtype
    k_init_detect<<<1, 256>>>((const unsigned char*)mask);

    // 1) v_p = V @ Wv^T + bv   [16384, 512]  (tensor core)
    k_tc_nt<0, true, false><<<dim3(4,128,1), 256>>>(v, Wv, bv, vp,
        D_, D_, 0, 0, 0, 1.f);

    // 2) defaults = uncond_q @ Wf^T + bf   [16, 512]  (tiny, SIMT)
    k_gemm_nt<0, true><<<dim3(4,1,1), 256>>>(uncond_q, Wf, bf, defv,
        B_, D_, D_, 1.f);

    // 3) scores = Q @ K^T / sqrt(D)  per batch, with global min/max (tensor)
    k_tc_nt<0, false, true><<<dim3(8,8,B_), 256>>>(q, k, nullptr, scores,
        LK_, D_, sQ, sK, sS, inv_sqrt_d);

    // 4) fb = EMA(fallback, (max+min)/2)
    k_fb<<<1, 32>>>(fallback);

    // 5) masked softmax over [scores, fb] per row; weights in place + fbw
    k_softmax<<<NROW_, 256>>>(scores, fbw, mask);

    // 6) out = weights @ v_p + fbw * defaults   (tensor, NN)
    k_tc_nn_attn<<<dim3(4,8,B_), 256>>>(scores, vp, attn,
        D_, LK_, sS, sK, sQ, fbw, defv);

    // 7) scorer on out (tensor)
    k_tc_nt<1, true, false><<<dim3(4,128,1), 256>>>(attn, W1, b1, h1,
        D_, D_, 0, 0, 0, 1.f);
    k_tc_nt<1, true, false><<<dim3(2,128,1), 256>>>(h1, W2, b2, h2,
        D_/2, D_, 0, 0, 0, 1.f);

    // 8) scorer on defaults (tiny, SIMT)
    k_gemm_nt<1, true><<<dim3(4,1,1), 256>>>(defv, W1, b1, dh1,
        B_, D_, D_, 1.f);
    k_gemm_nt<1, true><<<dim3(2,1,1), 256>>>(dh1, W2, b2, dh2,
        B_, D_/2, D_, 1.f);

    // 9) final tanh layers -> outputs (main [16384], defaults [16])
    float* out = (float*)d_out;
    k_scorer3<<<NROW_/8, 256>>>(h2, W3, b3, out, NROW_);
    if (out_size >= NROW_ + B_)
        k_scorer3<<<2, 256>>>(dh2, W3, b3, out + NROW_, B_);
}

// round 3
// speedup vs baseline: 2.6011x; 1.2555x over previous
#include <cuda_runtime.h>
#include <math.h>

#define D_ 512
#define B_ 16
#define LQ_ 1024
#define LK_ 1024
#define NROW_ (B_*LQ_)   // 16384

// ---------------- scratch (static device globals; no allocations) ----------
__device__ float g_vp[B_*LK_*D_];                  // 33.5 MB
__device__ float g_scores[(long long)B_*LQ_*LK_];  // 67 MB (reused in-place for weights)
__device__ float g_fbw[B_*LQ_];
__device__ float g_attn[NROW_*D_];
__device__ float g_h1[NROW_*D_];
__device__ float g_h2[NROW_*(D_/2)];
__device__ float g_def[B_*D_];
__device__ float g_dh1[B_*D_];
__device__ float g_dh2[B_*(D_/2)];
__device__ unsigned g_umax;
__device__ unsigned g_umin;
__device__ float g_fb;
__device__ int g_maskmode;

// ---------------- helpers ---------------------------------------------------
__device__ __forceinline__ unsigned fmap(float f){
    unsigned u = __float_as_uint(f);
    return (u & 0x80000000u) ? ~u : (u | 0x80000000u);
}
__device__ __forceinline__ float funmap(unsigned m){
    return (m & 0x80000000u) ? __uint_as_float(m ^ 0x80000000u)
                             : __uint_as_float(~m);
}

#define TFCVT(d,s) asm("cvt.rna.tf32.f32 %0, %1;" : "=r"(d) : "f"(s))
#define CPA16(saddr, gptr) asm volatile("cp.async.cg.shared.global [%0], [%1], 16;\n" :: "r"(saddr), "l"(gptr))
#define CPA_COMMIT() asm volatile("cp.async.commit_group;\n" ::: "memory")
#define CPA_WAIT1() asm volatile("cp.async.wait_group 1;\n" ::: "memory")

#define MMA_TF32(acc, a, b) \
    asm volatile( \
        "mma.sync.aligned.m16n8k8.row.col.f32.tf32.tf32.f32 " \
        "{%0,%1,%2,%3}, {%4,%5,%6,%7}, {%8,%9}, {%0,%1,%2,%3};" \
        : "+f"(acc[0]), "+f"(acc[1]), "+f"(acc[2]), "+f"(acc[3]) \
        : "r"(a[0]), "r"(a[1]), "r"(a[2]), "r"(a[3]), "r"(b[0]), "r"(b[1]))

// ---------------- init + mask dtype detection ------------------------------
__global__ void k_init_detect(const unsigned char* __restrict__ mb){
    __shared__ int sGE2, sOff;
    int tid = threadIdx.x;
    if (tid == 0){ sGE2 = 0; sOff = 0; g_umax = 0u; g_umin = 0xFFFFFFFFu; }
    __syncthreads();
    int ge2 = 0, off = 0;
    for (int i = tid; i < B_*LK_; i += blockDim.x){
        unsigned char c = mb[i];
        if (c > 1) ge2 = 1;
        else if (c == 1 && (i & 3)) off = 1;
    }
    if (ge2) sGE2 = 1;
    if (off) sOff = 1;
    __syncthreads();
    if (tid == 0) g_maskmode = sGE2 ? 2 : (sOff ? 0 : 1);
}

// =================== pipelined tf32 NT GEMM (tensor core) ==================
// C[m,n] = scale*sum_k A[m,k]*B[n,k] (+bias,+relu,+global minmax)
// Block tile 128(M) x 256(N), BK=32, 3-stage cp.async pipeline.
// 8 warps as 2(M) x 4(N); warp tile 64x64 = 4 x 8 m16n8k8 fragments.
// Requires M%128==0, N%256==0, K%32==0.
#define AS_STRIDE 36
#define BS_STRIDE 36
#define AS_WORDS (128*AS_STRIDE)       // per stage
#define BS_WORDS (256*BS_STRIDE)
#define NT_SMEM_BYTES (3*(AS_WORDS+BS_WORDS)*4)

template<int ACT, bool BIAS, bool MINMAX>
__global__ void __launch_bounds__(256, 1)
k_tc2_nt(const float* __restrict__ A, const float* __restrict__ Bm,
         const float* __restrict__ bias, float* __restrict__ C,
         int N, int K, long long sA, long long sB, long long sC, float scale)
{
    extern __shared__ float dsm[];
    __shared__ float red[512];

    const int bz = blockIdx.z;
    A  += (long long)bz * sA;
    Bm += (long long)bz * sB;
    C  += (long long)bz * sC;

    const int m0 = blockIdx.y * 128, n0 = blockIdx.x * 256;
    const int tid = threadIdx.x, lane = tid & 31, warp = tid >> 5;
    const int rbase = (warp & 1) * 64;
    const int cbase = (warp >> 1) * 64;
    const int grp = lane >> 2, qd = lane & 3;

    float* As = dsm;
    float* Bs = dsm + 3*AS_WORDS;
    const unsigned asu = (unsigned)__cvta_generic_to_shared(As);
    const unsigned bsu = (unsigned)__cvta_generic_to_shared(Bs);

    const int niter = K >> 5;

    auto load_stage = [&](int g){
        const int buf = g % 3;
        const int k0 = g << 5;
        const unsigned ab = asu + buf * (AS_WORDS*4);
        const unsigned bb = bsu + buf * (BS_WORDS*4);
        #pragma unroll
        for (int i = 0; i < 4; i++){
            int id = tid + 256*i, row = id >> 3, ch = (id & 7) * 4;
            CPA16(ab + (unsigned)(row*AS_STRIDE + ch)*4,
                  A + (long long)(m0 + row)*K + k0 + ch);
        }
        #pragma unroll
        for (int i = 0; i < 8; i++){
            int id = tid + 256*i, row = id >> 3, ch = (id & 7) * 4;
            CPA16(bb + (unsigned)(row*BS_STRIDE + ch)*4,
                  Bm + (long long)(n0 + row)*K + k0 + ch);
        }
    };

    float acc[4][8][4];
    #pragma unroll
    for (int mt = 0; mt < 4; mt++)
        #pragma unroll
        for (int u = 0; u < 8; u++)
            #pragma unroll
            for (int r = 0; r < 4; r++) acc[mt][u][r] = 0.f;

    load_stage(0); CPA_COMMIT();
    load_stage(1); CPA_COMMIT();

    for (int it = 0; it < niter; ++it){
        CPA_WAIT1();
        __syncthreads();
        const float* As_s = As + (it % 3)*AS_WORDS;
        const float* Bs_s = Bs + (it % 3)*BS_WORDS;
        #pragma unroll
        for (int kk = 0; kk < 32; kk += 8){
            unsigned a[4][4], b[8][2];
            #pragma unroll
            for (int mt = 0; mt < 4; mt++){
                const int m = rbase + mt*16 + grp;
                TFCVT(a[mt][0], As_s[m*AS_STRIDE + kk + qd]);
                TFCVT(a[mt][1], As_s[(m+8)*AS_STRIDE + kk + qd]);
                TFCVT(a[mt][2], As_s[m*AS_STRIDE + kk + qd + 4]);
                TFCVT(a[mt][3], As_s[(m+8)*AS_STRIDE + kk + qd + 4]);
            }
            #pragma unroll
            for (int u = 0; u < 8; u++){
                const int n = cbase + u*8 + grp;
                TFCVT(b[u][0], Bs_s[n*BS_STRIDE + kk + qd]);
                TFCVT(b[u][1], Bs_s[n*BS_STRIDE + kk + qd + 4]);
            }
            #pragma unroll
            for (int mt = 0; mt < 4; mt++)
                #pragma unroll
                for (int u = 0; u < 8; u++)
                    MMA_TF32(acc[mt][u], a[mt], b[u]);
        }
        __syncthreads();
        if (it + 2 < niter) load_stage(it + 2);
        CPA_COMMIT();
    }

    float lmax = -INFINITY, lmin = INFINITY;
    #pragma unroll
    for (int mt = 0; mt < 4; mt++){
        #pragma unroll
        for (int u = 0; u < 8; u++){
            const int row = m0 + rbase + mt*16 + grp;
            const int col = n0 + cbase + u*8 + qd*2;
            float v0 = acc[mt][u][0]*scale, v1 = acc[mt][u][1]*scale;
            float v2 = acc[mt][u][2]*scale, v3 = acc[mt][u][3]*scale;
            if (BIAS){
                float b0 = bias[col], b1 = bias[col+1];
                v0 += b0; v1 += b1; v2 += b0; v3 += b1;
            }
            if (ACT == 1){
                v0 = fmaxf(v0,0.f); v1 = fmaxf(v1,0.f);
                v2 = fmaxf(v2,0.f); v3 = fmaxf(v3,0.f);
            }
            *(float2*)(C + (long long)row*N + col)     = make_float2(v0, v1);
            *(float2*)(C + (long long)(row+8)*N + col) = make_float2(v2, v3);
            if (MINMAX){
                lmax = fmaxf(fmaxf(lmax, fmaxf(v0,v1)), fmaxf(v2,v3));
                lmin = fminf(fminf(lmin, fminf(v0,v1)), fminf(v2,v3));
            }
        }
    }
    if (MINMAX){
        red[tid] = lmax; red[256+tid] = lmin;
        __syncthreads();
        for (int st = 128; st > 0; st >>= 1){
            if (tid < st){
                red[tid]     = fmaxf(red[tid],     red[tid+st]);
                red[256+tid] = fminf(red[256+tid], red[256+tid+st]);
            }
            __syncthreads();
        }
        if (tid == 0){
            atomicMax(&g_umax, fmap(red[0]));
            atomicMin(&g_umin, fmap(red[256]));
        }
    }
}

// =================== pipelined tf32 NN GEMM (attention output) =============
// C[m,n] = sum_k A[m,k]*B[k,n] + fbw[m]*defv[n]
#define BSN_STRIDE 260
#define BSN_WORDS (32*BSN_STRIDE)
#define NN_SMEM_BYTES (3*(AS_WORDS+BSN_WORDS)*4)

__global__ void __launch_bounds__(256, 1)
k_tc2_nn_attn(const float* __restrict__ A, const float* __restrict__ Bm,
              float* __restrict__ C, int N, int K,
              long long sA, long long sB, long long sC,
              const float* __restrict__ fbw, const float* __restrict__ defv)
{
    extern __shared__ float dsm[];

    const int bz = blockIdx.z;
    A  += (long long)bz * sA;
    Bm += (long long)bz * sB;
    C  += (long long)bz * sC;

    const int m0 = blockIdx.y * 128, n0 = blockIdx.x * 256;
    const int tid = threadIdx.x, lane = tid & 31, warp = tid >> 5;
    const int rbase = (warp & 1) * 64;
    const int cbase = (warp >> 1) * 64;
    const int grp = lane >> 2, qd = lane & 3;

    float* As = dsm;
    float* Bs = dsm + 3*AS_WORDS;
    const unsigned asu = (unsigned)__cvta_generic_to_shared(As);
    const unsigned bsu = (unsigned)__cvta_generic_to_shared(Bs);

    const int niter = K >> 5;

    auto load_stage = [&](int g){
        const int buf = g % 3;
        const int k0 = g << 5;
        const unsigned ab = asu + buf * (AS_WORDS*4);
        const unsigned bb = bsu + buf * (BSN_WORDS*4);
        #pragma unroll
        for (int i = 0; i < 4; i++){
            int id = tid + 256*i, row = id >> 3, ch = (id & 7) * 4;
            CPA16(ab + (unsigned)(row*AS_STRIDE + ch)*4,
                  A + (long long)(m0 + row)*K + k0 + ch);
        }
        #pragma unroll
        for (int i = 0; i < 8; i++){
            int id = tid + 256*i, krow = id >> 6, nch = (id & 63) * 4;
            CPA16(bb + (unsigned)(krow*BSN_STRIDE + nch)*4,
                  Bm + (long long)(k0 + krow)*N + n0 + nch);
        }
    };

    float acc[4][8][4];
    #pragma unroll
    for (int mt = 0; mt < 4; mt++)
        #pragma unroll
        for (int u = 0; u < 8; u++)
            #pragma unroll
            for (int r = 0; r < 4; r++) acc[mt][u][r] = 0.f;

    load_stage(0); CPA_COMMIT();
    load_stage(1); CPA_COMMIT();

    for (int it = 0; it < niter; ++it){
        CPA_WAIT1();
        __syncthreads();
        const float* As_s = As + (it % 3)*AS_WORDS;
        const float* Bs_s = Bs + (it % 3)*BSN_WORDS;
        #pragma unroll
        for (int kk = 0; kk < 32; kk += 8){
            unsigned a[4][4], b[8][2];
            #pragma unroll
            for (int mt = 0; mt < 4; mt++){
                const int m = rbase + mt*16 + grp;
                TFCVT(a[mt][0], As_s[m*AS_STRIDE + kk + qd]);
                TFCVT(a[mt][1], As_s[(m+8)*AS_STRIDE + kk + qd]);
                TFCVT(a[mt][2], As_s[m*AS_STRIDE + kk + qd + 4]);
                TFCVT(a[mt][3], As_s[(m+8)*AS_STRIDE + kk + qd + 4]);
            }
            #pragma unroll
            for (int u = 0; u < 8; u++){
                const int n = cbase + u*8 + grp;
                TFCVT(b[u][0], Bs_s[(kk+qd)*BSN_STRIDE + n]);
                TFCVT(b[u][1], Bs_s[(kk+qd+4)*BSN_STRIDE + n]);
            }
            #pragma unroll
            for (int mt = 0; mt < 4; mt++)
                #pragma unroll
                for (int u = 0; u < 8; u++)
                    MMA_TF32(acc[mt][u], a[mt], b[u]);
        }
        __syncthreads();
        if (it + 2 < niter) load_stage(it + 2);
        CPA_COMMIT();
    }

    #pragma unroll
    for (int mt = 0; mt < 4; mt++){
        const int row = m0 + rbase + mt*16 + grp;
        const float fw0 = fbw[bz*LQ_ + row], fw1 = fbw[bz*LQ_ + row + 8];
        #pragma unroll
        for (int u = 0; u < 8; u++){
            const int col = n0 + cbase + u*8 + qd*2;
            const float d0 = defv[bz*D_ + col], d1 = defv[bz*D_ + col + 1];
            *(float2*)(C + (long long)row*N + col) =
                make_float2(acc[mt][u][0] + fw0*d0, acc[mt][u][1] + fw0*d1);
            *(float2*)(C + (long long)(row+8)*N + col) =
                make_float2(acc[mt][u][2] + fw1*d0, acc[mt][u][3] + fw1*d1);
        }
    }
}

// ---------------- legacy SIMT NT GEMM (for tiny M=16 GEMMs) ----------------
template<int ACT, bool BIAS>
__global__ void __launch_bounds__(256)
k_gemm_nt(const float* __restrict__ A, const float* __restrict__ Bm,
          const float* __restrict__ bias, float* __restrict__ C,
          int M, int N, int K, float scale)
{
    __shared__ __align__(16) float As[8][128];
    __shared__ __align__(16) float Bs[8][128];

    const int m0 = blockIdx.y * 128, n0 = blockIdx.x * 128;
    const int tid = threadIdx.x;
    const int tx = tid & 15, ty = tid >> 4;
    const int lrow = tid >> 1;
    const int lcol = (tid & 1) * 4;

    float acc[8][8];
    #pragma unroll
    for (int i = 0; i < 8; i++)
        #pragma unroll
        for (int j = 0; j < 8; j++) acc[i][j] = 0.f;

    for (int k0 = 0; k0 < K; k0 += 8){
        float4 av = make_float4(0.f,0.f,0.f,0.f);
        float4 bv = make_float4(0.f,0.f,0.f,0.f);
        if (m0 + lrow < M) av = *(const float4*)(A  + (long long)(m0+lrow)*K + (k0+lcol));
        if (n0 + lrow < N) bv = *(const float4*)(Bm + (long long)(n0+lrow)*K + (k0+lcol));
        As[lcol+0][lrow]=av.x; As[lcol+1][lrow]=av.y; As[lcol+2][lrow]=av.z; As[lcol+3][lrow]=av.w;
        Bs[lcol+0][lrow]=bv.x; Bs[lcol+1][lrow]=bv.y; Bs[lcol+2][lrow]=bv.z; Bs[lcol+3][lrow]=bv.w;
        __syncthreads();
        #pragma unroll
        for (int kk = 0; kk < 8; kk++){
            float4 a0 = *(const float4*)&As[kk][ty*8];
            float4 a1 = *(const float4*)&As[kk][ty*8+4];
            float4 b0 = *(const float4*)&Bs[kk][tx*8];
            float4 b1 = *(const float4*)&Bs[kk][tx*8+4];
            float a[8] = {a0.x,a0.y,a0.z,a0.w,a1.x,a1.y,a1.z,a1.w};
            float b[8] = {b0.x,b0.y,b0.z,b0.w,b1.x,b1.y,b1.z,b1.w};
            #pragma unroll
            for (int i = 0; i < 8; i++)
                #pragma unroll
                for (int j = 0; j < 8; j++)
                    acc[i][j] = fmaf(a[i], b[j], acc[i][j]);
        }
        __syncthreads();
    }

    #pragma unroll
    for (int i = 0; i < 8; i++){
        int m = m0 + ty*8 + i;
        if (m < M){
            #pragma unroll
            for (int j = 0; j < 8; j++){
                int n = n0 + tx*8 + j;
                if (n < N){
                    float v = acc[i][j] * scale;
                    if (BIAS) v += bias[n];
                    if (ACT == 1) v = fmaxf(v, 0.f);
                    C[(long long)m * N + n] = v;
                }
            }
        }
    }
}

// ---------------- fallback-score EMA ---------------------------------------
__global__ void k_fb(const float* __restrict__ fallback){
    if (threadIdx.x == 0){
        float bmax = funmap(g_umax), bmin = funmap(g_umin);
        const float M_ = 0.99f;
        g_fb = M_ * fallback[0] + (1.0f - M_) * ((bmax + bmin) * 0.5f);
    }
}

// ---------------- row softmax (in place), appended fallback column ---------
__global__ void __launch_bounds__(256)
k_softmax(float* __restrict__ scores, float* __restrict__ fbw,
          const void* __restrict__ maskp)
{
    __shared__ float red[256];
    const int row = blockIdx.x;
    const int b = row >> 10;
    const int tid = threadIdx.x;
    float* s = scores + (long long)row * LK_;
    const int mode = g_maskmode;
    const float fb = g_fb;

    float4 v = ((const float4*)s)[tid];
    float x[4] = {v.x, v.y, v.z, v.w};
    int mk[4];
    const int base = b * LK_ + tid * 4;
    if (mode == 0){
        uchar4 m4 = ((const uchar4*)maskp)[base >> 2];
        mk[0]=m4.x!=0; mk[1]=m4.y!=0; mk[2]=m4.z!=0; mk[3]=m4.w!=0;
    } else if (mode == 1){
        int4 m4 = ((const int4*)maskp)[base >> 2];
        mk[0]=m4.x!=0; mk[1]=m4.y!=0; mk[2]=m4.z!=0; mk[3]=m4.w!=0;
    } else {
        float4 m4 = ((const float4*)maskp)[base >> 2];
        mk[0]=m4.x!=0.f; mk[1]=m4.y!=0.f; mk[2]=m4.z!=0.f; mk[3]=m4.w!=0.f;
    }

    float lmax = fb;
    #pragma unroll
    for (int c = 0; c < 4; c++) if (!mk[c]) lmax = fmaxf(lmax, x[c]);
    red[tid] = lmax; __syncthreads();
    for (int st = 128; st > 0; st >>= 1){
        if (tid < st) red[tid] = fmaxf(red[tid], red[tid+st]);
        __syncthreads();
    }
    const float m = red[0];
    __syncthreads();

    float e[4]; float lsum = 0.f;
    #pragma unroll
    for (int c = 0; c < 4; c++){
        e[c] = mk[c] ? 0.f : expf(x[c] - m);
        lsum += e[c];
    }
    red[tid] = lsum; __syncthreads();
    for (int st = 128; st > 0; st >>= 1){
        if (tid < st) red[tid] += red[tid+st];
        __syncthreads();
    }
    const float fbe = expf(fb - m);
    const float inv = 1.f / (red[0] + fbe);
    ((float4*)s)[tid] = make_float4(e[0]*inv, e[1]*inv, e[2]*inv, e[3]*inv);
    if (tid == 0) fbw[row] = fbe * inv;
}

// ---------------- final scorer layer: tanh(h2 @ W3^T + b3) -----------------
__global__ void k_scorer3(const float* __restrict__ H2, const float* __restrict__ W3,
                          const float* __restrict__ b3, float* __restrict__ out, int M)
{
    int warp = threadIdx.x >> 5, lane = threadIdx.x & 31;
    int row = blockIdx.x * 8 + warp;
    if (row >= M) return;
    const float* h = H2 + (long long)row * (D_/2);
    float sum = 0.f;
    #pragma unroll
    for (int t = 0; t < 8; t++){
        int j = lane + t*32;
        sum = fmaf(h[j], W3[j], sum);
    }
    #pragma unroll
    for (int o = 16; o > 0; o >>= 1) sum += __shfl_down_sync(0xffffffffu, sum, o);
    if (lane == 0) out[row] = tanhf(sum + b3[0]);
}

// ---------------------------------------------------------------------------
extern "C" void kernel_launch(void* const* d_in, const int* in_sizes, int n_in,
                              void* d_out, int out_size)
{
    const float* uncond_q = (const float*)d_in[0];
    const float* q        = (const float*)d_in[1];
    const float* k        = (const float*)d_in[2];
    const float* v        = (const float*)d_in[3];
    const void*  mask     = d_in[4];
    const float* fallback = (const float*)d_in[5];
    const float* Wv = (const float*)d_in[6];
    const float* bv = (const float*)d_in[7];
    const float* Wf = (const float*)d_in[8];
    const float* bf = (const float*)d_in[9];
    const float* W1 = (const float*)d_in[10];
    const float* b1 = (const float*)d_in[11];
    const float* W2 = (const float*)d_in[12];
    const float* b2 = (const float*)d_in[13];
    const float* W3 = (const float*)d_in[14];
    const float* b3 = (const float*)d_in[15];

    float *vp, *scores, *fbw, *attn, *h1, *h2, *defv, *dh1, *dh2;
    cudaGetSymbolAddress((void**)&vp,     g_vp);
    cudaGetSymbolAddress((void**)&scores, g_scores);
    cudaGetSymbolAddress((void**)&fbw,    g_fbw);
    cudaGetSymbolAddress((void**)&attn,   g_attn);
    cudaGetSymbolAddress((void**)&h1,     g_h1);
    cudaGetSymbolAddress((void**)&h2,     g_h2);
    cudaGetSymbolAddress((void**)&defv,   g_def);
    cudaGetSymbolAddress((void**)&dh1,    g_dh1);
    cudaGetSymbolAddress((void**)&dh2,    g_dh2);

    // opt in to >48KB dynamic smem (host-side attribute, capture-safe)
    cudaFuncSetAttribute(k_tc2_nt<0,true,false>,
        cudaFuncAttributeMaxDynamicSharedMemorySize, NT_SMEM_BYTES);
    cudaFuncSetAttribute(k_tc2_nt<0,false,true>,
        cudaFuncAttributeMaxDynamicSharedMemorySize, NT_SMEM_BYTES);
    cudaFuncSetAttribute(k_tc2_nt<1,true,false>,
        cudaFuncAttributeMaxDynamicSharedMemorySize, NT_SMEM_BYTES);
    cudaFuncSetAttribute(k_tc2_nn_attn,
        cudaFuncAttributeMaxDynamicSharedMemorySize, NN_SMEM_BYTES);

    const float inv_sqrt_d = 0.04419417382415922f; // 1/sqrt(512)
    const long long sQ = (long long)LQ_ * D_;
    const long long sK = (long long)LK_ * D_;
    const long long sS = (long long)LQ_ * LK_;

    // 0) init min/max + detect mask dtype
    k_init_detect<<<1, 256>>>((const unsigned char*)mask);

    // 1) v_p = V @ Wv^T + bv   [16384, 512]
    k_tc2_nt<0, true, false><<<dim3(2,128,1), 256, NT_SMEM_BYTES>>>(
        v, Wv, bv, vp, D_, D_, 0, 0, 0, 1.f);

    // 2) defaults = uncond_q @ Wf^T + bf   [16, 512]  (tiny, SIMT)
    k_gemm_nt<0, true><<<dim3(4,1,1), 256>>>(uncond_q, Wf, bf, defv,
        B_, D_, D_, 1.f);

    // 3) scores = Q @ K^T / sqrt(D)  per batch, with global min/max
    k_tc2_nt<0, false, true><<<dim3(4,8,B_), 256, NT_SMEM_BYTES>>>(
        q, k, nullptr, scores, LK_, D_, sQ, sK, sS, inv_sqrt_d);

    // 4) fb = EMA(fallback, (max+min)/2)
    k_fb<<<1, 32>>>(fallback);

    // 5) masked softmax over [scores, fb] per row; weights in place + fbw
    k_softmax<<<NROW_, 256>>>(scores, fbw, mask);

    // 6) out = weights @ v_p + fbw * defaults   (NN, K=1024)
    k_tc2_nn_attn<<<dim3(2,8,B_), 256, NN_SMEM_BYTES>>>(
        scores, vp, attn, D_, LK_, sS, sK, sQ, fbw, defv);

    // 7) scorer on out
    k_tc2_nt<1, true, false><<<dim3(2,128,1), 256, NT_SMEM_BYTES>>>(
        attn, W1, b1, h1, D_, D_, 0, 0, 0, 1.f);
    k_tc2_nt<1, true, false><<<dim3(1,128,1), 256, NT_SMEM_BYTES>>>(
        h1, W2, b2, h2, D_/2, D_, 0, 0, 0, 1.f);

    // 8) scorer on defaults (tiny, SIMT)
    k_gemm_nt<1, true><<<dim3(4,1,1), 256>>>(defv, W1, b1, dh1,
        B_, D_, D_, 1.f);
    k_gemm_nt<1, true><<<dim3(2,1,1), 256>>>(dh1, W2, b2, dh2,
        B_, D_/2, D_, 1.f);

    // 9) final tanh layers -> outputs (main [16384], defaults [16])
    float* out = (float*)d_out;
    k_scorer3<<<NROW_/8, 256>>>(h2, W3, b3, out, NROW_);
    if (out_size >= NROW_ + B_)
        k_scorer3<<<2, 256>>>(dh2, W3, b3, out + NROW_, B_);
}

// round 4
// speedup vs baseline: 2.6088x; 1.0030x over previous
#include <cuda_runtime.h>
#include <math.h>

#define D_ 512
#define B_ 16
#define LQ_ 1024
#define LK_ 1024
#define NROW_ (B_*LQ_)   // 16384

// ---------------- scratch (static device globals; no allocations) ----------
__device__ float g_vp[B_*LK_*D_];                  // 33.5 MB
__device__ float g_scores[(long long)B_*LQ_*LK_];  // 67 MB (reused in-place for weights)
__device__ float g_fbw[B_*LQ_];
__device__ float g_attn[NROW_*D_];
__device__ float g_h1[NROW_*D_];
__device__ float g_h2[NROW_*(D_/2)];
__device__ float g_def[B_*D_];
__device__ float g_dh1[B_*D_];
__device__ float g_dh2[B_*(D_/2)];
__device__ unsigned g_umax;
__device__ unsigned g_umin;
__device__ float g_fb;
__device__ int g_maskmode;

// ---------------- helpers ---------------------------------------------------
__device__ __forceinline__ unsigned fmap(float f){
    unsigned u = __float_as_uint(f);
    return (u & 0x80000000u) ? ~u : (u | 0x80000000u);
}
__device__ __forceinline__ float funmap(unsigned m){
    return (m & 0x80000000u) ? __uint_as_float(m ^ 0x80000000u)
                             : __uint_as_float(~m);
}

#define TFCVT(d,s) asm("cvt.rna.tf32.f32 %0, %1;" : "=r"(d) : "f"(s))
#define CPA16(saddr, gptr) asm volatile("cp.async.cg.shared.global [%0], [%1], 16;\n" :: "r"(saddr), "l"(gptr))
#define CPA_COMMIT() asm volatile("cp.async.commit_group;\n" ::: "memory")
#define CPA_WAIT1() asm volatile("cp.async.wait_group 1;\n" ::: "memory")

#define MMA_TF32(acc, a, b) \
    asm volatile( \
        "mma.sync.aligned.m16n8k8.row.col.f32.tf32.tf32.f32 " \
        "{%0,%1,%2,%3}, {%4,%5,%6,%7}, {%8,%9}, {%0,%1,%2,%3};" \
        : "+f"(acc[0]), "+f"(acc[1]), "+f"(acc[2]), "+f"(acc[3]) \
        : "r"(a[0]), "r"(a[1]), "r"(a[2]), "r"(a[3]), "r"(b[0]), "r"(b[1]))

// ---------------- init + mask dtype detection ------------------------------
__global__ void k_init_detect(const unsigned char* __restrict__ mb){
    __shared__ int sGE2, sOff;
    int tid = threadIdx.x;
    if (tid == 0){ sGE2 = 0; sOff = 0; g_umax = 0u; g_umin = 0xFFFFFFFFu; }
    __syncthreads();
    int ge2 = 0, off = 0;
    for (int i = tid; i < B_*LK_; i += blockDim.x){
        unsigned char c = mb[i];
        if (c > 1) ge2 = 1;
        else if (c == 1 && (i & 3)) off = 1;
    }
    if (ge2) sGE2 = 1;
    if (off) sOff = 1;
    __syncthreads();
    if (tid == 0) g_maskmode = sGE2 ? 2 : (sOff ? 0 : 1);
}

// =================== pipelined tf32 NT GEMM (tensor core) ==================
// C[m,n] = scale*sum_k A[m,k]*B[n,k] (+bias,+relu,+global minmax)
// Block tile 128(M) x 256(N), BK=32, 3-stage cp.async pipeline.
// 8 warps as 2(M) x 4(N); warp tile 64x64 = 4 x 8 m16n8k8 fragments.
// Requires M%128==0, N%256==0, K%32==0.
#define AS_STRIDE 36
#define BS_STRIDE 36
#define AS_WORDS (128*AS_STRIDE)       // per stage
#define BS_WORDS (256*BS_STRIDE)
#define NT_SMEM_BYTES (3*(AS_WORDS+BS_WORDS)*4)

template<int ACT, bool BIAS, bool MINMAX>
__global__ void __launch_bounds__(256, 1)
k_tc2_nt(const float* __restrict__ A, const float* __restrict__ Bm,
         const float* __restrict__ bias, float* __restrict__ C,
         int N, int K, long long sA, long long sB, long long sC, float scale)
{
    extern __shared__ float dsm[];
    __shared__ float red[512];

    const int bz = blockIdx.z;
    A  += (long long)bz * sA;
    Bm += (long long)bz * sB;
    C  += (long long)bz * sC;

    const int m0 = blockIdx.y * 128, n0 = blockIdx.x * 256;
    const int tid = threadIdx.x, lane = tid & 31, warp = tid >> 5;
    const int rbase = (warp & 1) * 64;
    const int cbase = (warp >> 1) * 64;
    const int grp = lane >> 2, qd = lane & 3;

    float* As = dsm;
    float* Bs = dsm + 3*AS_WORDS;
    const unsigned asu = (unsigned)__cvta_generic_to_shared(As);
    const unsigned bsu = (unsigned)__cvta_generic_to_shared(Bs);

    const int niter = K >> 5;

    auto load_stage = [&](int g){
        const int buf = g % 3;
        const int k0 = g << 5;
        const unsigned ab = asu + buf * (AS_WORDS*4);
        const unsigned bb = bsu + buf * (BS_WORDS*4);
        #pragma unroll
        for (int i = 0; i < 4; i++){
            int id = tid + 256*i, row = id >> 3, ch = (id & 7) * 4;
            CPA16(ab + (unsigned)(row*AS_STRIDE + ch)*4,
                  A + (long long)(m0 + row)*K + k0 + ch);
        }
        #pragma unroll
        for (int i = 0; i < 8; i++){
            int id = tid + 256*i, row = id >> 3, ch = (id & 7) * 4;
            CPA16(bb + (unsigned)(row*BS_STRIDE + ch)*4,
                  Bm + (long long)(n0 + row)*K + k0 + ch);
        }
    };

    float acc[4][8][4];
    #pragma unroll
    for (int mt = 0; mt < 4; mt++)
        #pragma unroll
        for (int u = 0; u < 8; u++)
            #pragma unroll
            for (int r = 0; r < 4; r++) acc[mt][u][r] = 0.f;

    load_stage(0); CPA_COMMIT();
    load_stage(1); CPA_COMMIT();

    for (int it = 0; it < niter; ++it){
        CPA_WAIT1();
        __syncthreads();
        const float* As_s = As + (it % 3)*AS_WORDS;
        const float* Bs_s = Bs + (it % 3)*BS_WORDS;
        #pragma unroll
        for (int kk = 0; kk < 32; kk += 8){
            unsigned a[4][4], b[8][2];
            #pragma unroll
            for (int mt = 0; mt < 4; mt++){
                const int m = rbase + mt*16 + grp;
                TFCVT(a[mt][0], As_s[m*AS_STRIDE + kk + qd]);
                TFCVT(a[mt][1], As_s[(m+8)*AS_STRIDE + kk + qd]);
                TFCVT(a[mt][2], As_s[m*AS_STRIDE + kk + qd + 4]);
                TFCVT(a[mt][3], As_s[(m+8)*AS_STRIDE + kk + qd + 4]);
            }
            #pragma unroll
            for (int u = 0; u < 8; u++){
                const int n = cbase + u*8 + grp;
                TFCVT(b[u][0], Bs_s[n*BS_STRIDE + kk + qd]);
                TFCVT(b[u][1], Bs_s[n*BS_STRIDE + kk + qd + 4]);
            }
            #pragma unroll
            for (int mt = 0; mt < 4; mt++)
                #pragma unroll
                for (int u = 0; u < 8; u++)
                    MMA_TF32(acc[mt][u], a[mt], b[u]);
        }
        __syncthreads();
        if (it + 2 < niter) load_stage(it + 2);
        CPA_COMMIT();
    }

    float lmax = -INFINITY, lmin = INFINITY;
    #pragma unroll
    for (int mt = 0; mt < 4; mt++){
        #pragma unroll
        for (int u = 0; u < 8; u++){
            const int row = m0 + rbase + mt*16 + grp;
            const int col = n0 + cbase + u*8 + qd*2;
            float v0 = acc[mt][u][0]*scale, v1 = acc[mt][u][1]*scale;
            float v2 = acc[mt][u][2]*scale, v3 = acc[mt][u][3]*scale;
            if (BIAS){
                float b0 = bias[col], b1 = bias[col+1];
                v0 += b0; v1 += b1; v2 += b0; v3 += b1;
            }
            if (ACT == 1){
                v0 = fmaxf(v0,0.f); v1 = fmaxf(v1,0.f);
                v2 = fmaxf(v2,0.f); v3 = fmaxf(v3,0.f);
            }
            *(float2*)(C + (long long)row*N + col)     = make_float2(v0, v1);
            *(float2*)(C + (long long)(row+8)*N + col) = make_float2(v2, v3);
            if (MINMAX){
                lmax = fmaxf(fmaxf(lmax, fmaxf(v0,v1)), fmaxf(v2,v3));
                lmin = fminf(fminf(lmin, fminf(v0,v1)), fminf(v2,v3));
            }
        }
    }
    if (MINMAX){
        red[tid] = lmax; red[256+tid] = lmin;
        __syncthreads();
        for (int st = 128; st > 0; st >>= 1){
            if (tid < st){
                red[tid]     = fmaxf(red[tid],     red[tid+st]);
                red[256+tid] = fminf(red[256+tid], red[256+tid+st]);
            }
            __syncthreads();
        }
        if (tid == 0){
            atomicMax(&g_umax, fmap(red[0]));
            atomicMin(&g_umin, fmap(red[256]));
        }
    }
}

// =================== pipelined tf32 NN GEMM (attention output) =============
// C[m,n] = sum_k A[m,k]*B[k,n] + fbw[m]*defv[n]
#define BSN_STRIDE 260
#define BSN_WORDS (32*BSN_STRIDE)
#define NN_SMEM_BYTES (3*(AS_WORDS+BSN_WORDS)*4)

__global__ void __launch_bounds__(256, 1)
k_tc2_nn_attn(const float* __restrict__ A, const float* __restrict__ Bm,
              float* __restrict__ C, int N, int K,
              long long sA, long long sB, long long sC,
              const float* __restrict__ fbw, const float* __restrict__ defv)
{
    extern __shared__ float dsm[];

    const int bz = blockIdx.z;
    A  += (long long)bz * sA;
    Bm += (long long)bz * sB;
    C  += (long long)bz * sC;

    const int m0 = blockIdx.y * 128, n0 = blockIdx.x * 256;
    const int tid = threadIdx.x, lane = tid & 31, warp = tid >> 5;
    const int rbase = (warp & 1) * 64;
    const int cbase = (warp >> 1) * 64;
    const int grp = lane >> 2, qd = lane & 3;

    float* As = dsm;
    float* Bs = dsm + 3*AS_WORDS;
    const unsigned asu = (unsigned)__cvta_generic_to_shared(As);
    const unsigned bsu = (unsigned)__cvta_generic_to_shared(Bs);

    const int niter = K >> 5;

    auto load_stage = [&](int g){
        const int buf = g % 3;
        const int k0 = g << 5;
        const unsigned ab = asu + buf * (AS_WORDS*4);
        const unsigned bb = bsu + buf * (BSN_WORDS*4);
        #pragma unroll
        for (int i = 0; i < 4; i++){
            int id = tid + 256*i, row = id >> 3, ch = (id & 7) * 4;
            CPA16(ab + (unsigned)(row*AS_STRIDE + ch)*4,
                  A + (long long)(m0 + row)*K + k0 + ch);
        }
        #pragma unroll
        for (int i = 0; i < 8; i++){
            int id = tid + 256*i, krow = id >> 6, nch = (id & 63) * 4;
            CPA16(bb + (unsigned)(krow*BSN_STRIDE + nch)*4,
                  Bm + (long long)(k0 + krow)*N + n0 + nch);
        }
    };

    float acc[4][8][4];
    #pragma unroll
    for (int mt = 0; mt < 4; mt++)
        #pragma unroll
        for (int u = 0; u < 8; u++)
            #pragma unroll
            for (int r = 0; r < 4; r++) acc[mt][u][r] = 0.f;

    load_stage(0); CPA_COMMIT();
    load_stage(1); CPA_COMMIT();

    for (int it = 0; it < niter; ++it){
        CPA_WAIT1();
        __syncthreads();
        const float* As_s = As + (it % 3)*AS_WORDS;
        const float* Bs_s = Bs + (it % 3)*BSN_WORDS;
        #pragma unroll
        for (int kk = 0; kk < 32; kk += 8){
            unsigned a[4][4], b[8][2];
            #pragma unroll
            for (int mt = 0; mt < 4; mt++){
                const int m = rbase + mt*16 + grp;
                TFCVT(a[mt][0], As_s[m*AS_STRIDE + kk + qd]);
                TFCVT(a[mt][1], As_s[(m+8)*AS_STRIDE + kk + qd]);
                TFCVT(a[mt][2], As_s[m*AS_STRIDE + kk + qd + 4]);
                TFCVT(a[mt][3], As_s[(m+8)*AS_STRIDE + kk + qd + 4]);
            }
            #pragma unroll
            for (int u = 0; u < 8; u++){
                const int n = cbase + u*8 + grp;
                TFCVT(b[u][0], Bs_s[(kk+qd)*BSN_STRIDE + n]);
                TFCVT(b[u][1], Bs_s[(kk+qd+4)*BSN_STRIDE + n]);
            }
            #pragma unroll
            for (int mt = 0; mt < 4; mt++)
                #pragma unroll
                for (int u = 0; u < 8; u++)
                    MMA_TF32(acc[mt][u], a[mt], b[u]);
        }
        __syncthreads();
        if (it + 2 < niter) load_stage(it + 2);
        CPA_COMMIT();
    }

    #pragma unroll
    for (int mt = 0; mt < 4; mt++){
        const int row = m0 + rbase + mt*16 + grp;
        const float fw0 = fbw[bz*LQ_ + row], fw1 = fbw[bz*LQ_ + row + 8];
        #pragma unroll
        for (int u = 0; u < 8; u++){
            const int col = n0 + cbase + u*8 + qd*2;
            const float d0 = defv[bz*D_ + col], d1 = defv[bz*D_ + col + 1];
            *(float2*)(C + (long long)row*N + col) =
                make_float2(acc[mt][u][0] + fw0*d0, acc[mt][u][1] + fw0*d1);
            *(float2*)(C + (long long)(row+8)*N + col) =
                make_float2(acc[mt][u][2] + fw1*d0, acc[mt][u][3] + fw1*d1);
        }
    }
}

// ---------------- legacy SIMT NT GEMM (for tiny M=16 GEMMs) ----------------
template<int ACT, bool BIAS>
__global__ void __launch_bounds__(256)
k_gemm_nt(const float* __restrict__ A, const float* __restrict__ Bm,
          const float* __restrict__ bias, float* __restrict__ C,
          int M, int N, int K, float scale)
{
    __shared__ __align__(16) float As[8][128];
    __shared__ __align__(16) float Bs[8][128];

    const int m0 = blockIdx.y * 128, n0 = blockIdx.x * 128;
    const int tid = threadIdx.x;
    const int tx = tid & 15, ty = tid >> 4;
    const int lrow = tid >> 1;
    const int lcol = (tid & 1) * 4;

    float acc[8][8];
    #pragma unroll
    for (int i = 0; i < 8; i++)
        #pragma unroll
        for (int j = 0; j < 8; j++) acc[i][j] = 0.f;

    for (int k0 = 0; k0 < K; k0 += 8){
        float4 av = make_float4(0.f,0.f,0.f,0.f);
        float4 bv = make_float4(0.f,0.f,0.f,0.f);
        if (m0 + lrow < M) av = *(const float4*)(A  + (long long)(m0+lrow)*K + (k0+lcol));
        if (n0 + lrow < N) bv = *(const float4*)(Bm + (long long)(n0+lrow)*K + (k0+lcol));
        As[lcol+0][lrow]=av.x; As[lcol+1][lrow]=av.y; As[lcol+2][lrow]=av.z; As[lcol+3][lrow]=av.w;
        Bs[lcol+0][lrow]=bv.x; Bs[lcol+1][lrow]=bv.y; Bs[lcol+2][lrow]=bv.z; Bs[lcol+3][lrow]=bv.w;
        __syncthreads();
        #pragma unroll
        for (int kk = 0; kk < 8; kk++){
            float4 a0 = *(const float4*)&As[kk][ty*8];
            float4 a1 = *(const float4*)&As[kk][ty*8+4];
            float4 b0 = *(const float4*)&Bs[kk][tx*8];
            float4 b1 = *(const float4*)&Bs[kk][tx*8+4];
            float a[8] = {a0.x,a0.y,a0.z,a0.w,a1.x,a1.y,a1.z,a1.w};
            float b[8] = {b0.x,b0.y,b0.z,b0.w,b1.x,b1.y,b1.z,b1.w};
            #pragma unroll
            for (int i = 0; i < 8; i++)
                #pragma unroll
                for (int j = 0; j < 8; j++)
                    acc[i][j] = fmaf(a[i], b[j], acc[i][j]);
        }
        __syncthreads();
    }

    #pragma unroll
    for (int i = 0; i < 8; i++){
        int m = m0 + ty*8 + i;
        if (m < M){
            #pragma unroll
            for (int j = 0; j < 8; j++){
                int n = n0 + tx*8 + j;
                if (n < N){
                    float v = acc[i][j] * scale;
                    if (BIAS) v += bias[n];
                    if (ACT == 1) v = fmaxf(v, 0.f);
                    C[(long long)m * N + n] = v;
                }
            }
        }
    }
}

// ---------------- fallback-score EMA ---------------------------------------
__global__ void k_fb(const float* __restrict__ fallback){
    if (threadIdx.x == 0){
        float bmax = funmap(g_umax), bmin = funmap(g_umin);
        const float M_ = 0.99f;
        g_fb = M_ * fallback[0] + (1.0f - M_) * ((bmax + bmin) * 0.5f);
    }
}

// ---------------- row softmax (in place), appended fallback column ---------
__global__ void __launch_bounds__(256)
k_softmax(float* __restrict__ scores, float* __restrict__ fbw,
          const void* __restrict__ maskp)
{
    __shared__ float red[256];
    const int row = blockIdx.x;
    const int b = row >> 10;
    const int tid = threadIdx.x;
    float* s = scores + (long long)row * LK_;
    const int mode = g_maskmode;
    const float fb = g_fb;

    float4 v = ((const float4*)s)[tid];
    float x[4] = {v.x, v.y, v.z, v.w};
    int mk[4];
    const int base = b * LK_ + tid * 4;
    if (mode == 0){
        uchar4 m4 = ((const uchar4*)maskp)[base >> 2];
        mk[0]=m4.x!=0; mk[1]=m4.y!=0; mk[2]=m4.z!=0; mk[3]=m4.w!=0;
    } else if (mode == 1){
        int4 m4 = ((const int4*)maskp)[base >> 2];
        mk[0]=m4.x!=0; mk[1]=m4.y!=0; mk[2]=m4.z!=0; mk[3]=m4.w!=0;
    } else {
        float4 m4 = ((const float4*)maskp)[base >> 2];
        mk[0]=m4.x!=0.f; mk[1]=m4.y!=0.f; mk[2]=m4.z!=0.f; mk[3]=m4.w!=0.f;
    }

    float lmax = fb;
    #pragma unroll
    for (int c = 0; c < 4; c++) if (!mk[c]) lmax = fmaxf(lmax, x[c]);
    red[tid] = lmax; __syncthreads();
    for (int st = 128; st > 0; st >>= 1){
        if (tid < st) red[tid] = fmaxf(red[tid], red[tid+st]);
        __syncthreads();
    }
    const float m = red[0];
    __syncthreads();

    float e[4]; float lsum = 0.f;
    #pragma unroll
    for (int c = 0; c < 4; c++){
        e[c] = mk[c] ? 0.f : expf(x[c] - m);
        lsum += e[c];
    }
    red[tid] = lsum; __syncthreads();
    for (int st = 128; st > 0; st >>= 1){
        if (tid < st) red[tid] += red[tid+st];
        __syncthreads();
    }
    const float fbe = expf(fb - m);
    const float inv = 1.f / (red[0] + fbe);
    ((float4*)s)[tid] = make_float4(e[0]*inv, e[1]*inv, e[2]*inv, e[3]*inv);
    if (tid == 0) fbw[row] = fbe * inv;
}

// ---------------- final scorer layer: tanh(h2 @ W3^T + b3) -----------------
__global__ void k_scorer3(const float* __restrict__ H2, const float* __restrict__ W3,
                          const float* __restrict__ b3, float* __restrict__ out, int M)
{
    int warp = threadIdx.x >> 5, lane = threadIdx.x & 31;
    int row = blockIdx.x * 8 + warp;
    if (row >= M) return;
    const float* h = H2 + (long long)row * (D_/2);
    float sum = 0.f;
    #pragma unroll
    for (int t = 0; t < 8; t++){
        int j = lane + t*32;
        sum = fmaf(h[j], W3[j], sum);
    }
    #pragma unroll
    for (int o = 16; o > 0; o >>= 1) sum += __shfl_down_sync(0xffffffffu, sum, o);
    if (lane == 0) out[row] = tanhf(sum + b3[0]);
}

// ---------------------------------------------------------------------------
extern "C" void kernel_launch(void* const* d_in, const int* in_sizes, int n_in,
                              void* d_out, int out_size)
{
    const float* uncond_q = (const float*)d_in[0];
    const float* q        = (const float*)d_in[1];
    const float* k        = (const float*)d_in[2];
    const float* v        = (const float*)d_in[3];
    const void*  mask     = d_in[4];
    const float* fallback = (const float*)d_in[5];
    const float* Wv = (const float*)d_in[6];
    const float* bv = (const float*)d_in[7];
    const float* Wf = (const float*)d_in[8];
    const float* bf = (const float*)d_in[9];
    const float* W1 = (const float*)d_in[10];
    const float* b1 = (const float*)d_in[11];
    const float* W2 = (const float*)d_in[12];
    const float* b2 = (const float*)d_in[13];
    const float* W3 = (const float*)d_in[14];
    const float* b3 = (const float*)d_in[15];

    float *vp, *scores, *fbw, *attn, *h1, *h2, *defv, *dh1, *dh2;
    cudaGetSymbolAddress((void**)&vp,     g_vp);
    cudaGetSymbolAddress((void**)&scores, g_scores);
    cudaGetSymbolAddress((void**)&fbw,    g_fbw);
    cudaGetSymbolAddress((void**)&attn,   g_attn);
    cudaGetSymbolAddress((void**)&h1,     g_h1);
    cudaGetSymbolAddress((void**)&h2,     g_h2);
    cudaGetSymbolAddress((void**)&defv,   g_def);
    cudaGetSymbolAddress((void**)&dh1,    g_dh1);
    cudaGetSymbolAddress((void**)&dh2,    g_dh2);

    // opt in to >48KB dynamic smem (host-side attribute, capture-safe)
    cudaFuncSetAttribute(k_tc2_nt<0,true,false>,
        cudaFuncAttributeMaxDynamicSharedMemorySize, NT_SMEM_BYTES);
    cudaFuncSetAttribute(k_tc2_nt<0,false,true>,
        cudaFuncAttributeMaxDynamicSharedMemorySize, NT_SMEM_BYTES);
    cudaFuncSetAttribute(k_tc2_nt<1,true,false>,
        cudaFuncAttributeMaxDynamicSharedMemorySize, NT_SMEM_BYTES);
    cudaFuncSetAttribute(k_tc2_nn_attn,
        cudaFuncAttributeMaxDynamicSharedMemorySize, NN_SMEM_BYTES);

    const float inv_sqrt_d = 0.04419417382415922f; // 1/sqrt(512)
    const long long sQ = (long long)LQ_ * D_;
    const long long sK = (long long)LK_ * D_;
    const long long sS = (long long)LQ_ * LK_;

    // 0) init min/max + detect mask dtype
    k_init_detect<<<1, 256>>>((const unsigned char*)mask);

    // 1) v_p = V @ Wv^T + bv   [16384, 512]
    k_tc2_nt<0, true, false><<<dim3(2,128,1), 256, NT_SMEM_BYTES>>>(
        v, Wv, bv, vp, D_, D_, 0, 0, 0, 1.f);

    // 2) defaults = uncond_q @ Wf^T + bf   [16, 512]  (tiny, SIMT)
    k_gemm_nt<0, true><<<dim3(4,1,1), 256>>>(uncond_q, Wf, bf, defv,
        B_, D_, D_, 1.f);

    // 3) scores = Q @ K^T / sqrt(D)  per batch, with global min/max
    k_tc2_nt<0, false, true><<<dim3(4,8,B_), 256, NT_SMEM_BYTES>>>(
        q, k, nullptr, scores, LK_, D_, sQ, sK, sS, inv_sqrt_d);

    // 4) fb = EMA(fallback, (max+min)/2)
    k_fb<<<1, 32>>>(fallback);

    // 5) masked softmax over [scores, fb] per row; weights in place + fbw
    k_softmax<<<NROW_, 256>>>(scores, fbw, mask);

    // 6) out = weights @ v_p + fbw * defaults   (NN, K=1024)
    k_tc2_nn_attn<<<dim3(2,8,B_), 256, NN_SMEM_BYTES>>>(
        scores, vp, attn, D_, LK_, sS, sK, sQ, fbw, defv);

    // 7) scorer on out
    k_tc2_nt<1, true, false><<<dim3(2,128,1), 256, NT_SMEM_BYTES>>>(
        attn, W1, b1, h1, D_, D_, 0, 0, 0, 1.f);
    k_tc2_nt<1, true, false><<<dim3(1,128,1), 256, NT_SMEM_BYTES>>>(
        h1, W2, b2, h2, D_/2, D_, 0, 0, 0, 1.f);

    // 8) scorer on defaults (tiny, SIMT)
    k_gemm_nt<1, true><<<dim3(4,1,1), 256>>>(defv, W1, b1, dh1,
        B_, D_, D_, 1.f);
    k_gemm_nt<1, true><<<dim3(2,1,1), 256>>>(dh1, W2, b2, dh2,
        B_, D_/2, D_, 1.f);

    // 9) final tanh layers -> outputs (main [16384], defaults [16])
    float* out = (float*)d_out;
    k_scorer3<<<NROW_/8, 256>>>(h2, W3, b3, out, NROW_);
    if (out_size >= NROW_ + B_)
        k_scorer3<<<2, 256>>>(dh2, W3, b3, out + NROW_, B_);
}

// round 6
// speedup vs baseline: 3.7253x; 1.4280x over previous
#include <cuda_runtime.h>
#include <math.h>
#include <stdint.h>

#define D_ 512
#define B_ 16
#define LQ_ 1024
#define LK_ 1024
#define NROW_ (B_*LQ_)

// ---------------- scratch globals (tf32-rounded, k-permuted planes) --------
__device__ __align__(16) float g_qp[NROW_*D_];
__device__ __align__(16) float g_kp[NROW_*D_];
__device__ __align__(16) float g_vpin[NROW_*D_];
__device__ __align__(16) float g_wvp[D_*D_];
__device__ __align__(16) float g_w1p[D_*D_];
__device__ __align__(16) float g_w2p[(D_/2)*D_];
__device__ __align__(16) float g_vp[NROW_*D_];
__device__ __align__(16) float g_vpt[B_*D_*LK_];
__device__ __align__(16) float g_scores[(long long)B_*LQ_*LK_];
__device__ __align__(16) float g_wt[(long long)B_*LQ_*LK_];
__device__ __align__(16) float g_attn[NROW_*D_];
__device__ __align__(16) float g_h1[NROW_*D_];
__device__ __align__(16) float g_h2[NROW_*(D_/2)];
__device__ float g_fbw[NROW_];
__device__ float g_def[B_*D_], g_dh1[B_*D_], g_dh2[B_*(D_/2)];
__device__ unsigned g_umax, g_umin;
__device__ float g_fb;
__device__ int g_maskmode;

// ---------------- helpers ---------------------------------------------------
__device__ __forceinline__ unsigned fmap(float f){
    unsigned u = __float_as_uint(f);
    return (u & 0x80000000u) ? ~u : (u | 0x80000000u);
}
__device__ __forceinline__ float funmap(unsigned m){
    return (m & 0x80000000u) ? __uint_as_float(m ^ 0x80000000u) : __uint_as_float(~m);
}
__device__ __forceinline__ float tf32r(float x){
    unsigned r; asm("cvt.rna.tf32.f32 %0, %1;" : "=r"(r) : "f"(x));
    return __uint_as_float(r);
}
__device__ __forceinline__ int kperm(int c){
    return (c & ~7) | ((c & 3) << 1) | ((c >> 2) & 1);
}
#define CPA16(sa, gp) asm volatile("cp.async.cg.shared.global [%0], [%1], 16;\n" :: "r"(sa), "l"(gp))
#define CPA_COMMIT() asm volatile("cp.async.commit_group;\n" ::: "memory")
#define CPA_WAIT1()  asm volatile("cp.async.wait_group 1;\n" ::: "memory")

#define MMA_TF32(acc, a0, a1, a2, a3, b0, b1) \
    asm volatile( \
        "mma.sync.aligned.m16n8k8.row.col.f32.tf32.tf32.f32 " \
        "{%0,%1,%2,%3}, {%4,%5,%6,%7}, {%8,%9}, {%0,%1,%2,%3};" \
        : "+f"((acc)[0]), "+f"((acc)[1]), "+f"((acc)[2]), "+f"((acc)[3]) \
        : "r"(a0), "r"(a1), "r"(a2), "r"(a3), "r"(b0), "r"(b1))

// ---------------- init + mask dtype detection ------------------------------
__global__ void k_init_detect(const unsigned char* __restrict__ mb){
    __shared__ int sGE2, sOff;
    int tid = threadIdx.x;
    if (tid == 0){ sGE2 = 0; sOff = 0; g_umax = 0u; g_umin = 0xFFFFFFFFu; }
    __syncthreads();
    int ge2 = 0, off = 0;
    for (int i = tid; i < B_*LK_; i += blockDim.x){
        unsigned char c = mb[i];
        if (c > 1) ge2 = 1;
        else if (c == 1 && (i & 3)) off = 1;
    }
    if (ge2) sGE2 = 1;
    if (off) sOff = 1;
    __syncthreads();
    if (tid == 0) g_maskmode = sGE2 ? 2 : (sOff ? 0 : 1);
}

// ---------------- f32 -> tf32-rounded, k-permuted --------------------------
__global__ void k_cvtperm(const float4* __restrict__ x, float* __restrict__ y, int n4){
    int i = blockIdx.x * blockDim.x + threadIdx.x;
    if (i >= n4) return;
    float4 v = x[i];
    int base = i * 4;
    y[kperm(base  )] = tf32r(v.x);
    y[kperm(base+1)] = tf32r(v.y);
    y[kperm(base+2)] = tf32r(v.z);
    y[kperm(base+3)] = tf32r(v.w);
}

// ---------------- vp transpose+round+permute: [B][Lk][D] -> [B][D][Lk] -----
__global__ void k_trcvt(const float* __restrict__ vp, float* __restrict__ vt){
    __shared__ float t[32][33];
    const int bz = blockIdx.z;
    const int d0 = blockIdx.x * 32, l0 = blockIdx.y * 32;
    const int tx = threadIdx.x, ty = threadIdx.y;   // (32,8)
    const float* src = vp + (long long)bz * LK_ * D_;
    #pragma unroll
    for (int r = 0; r < 32; r += 8)
        t[ty+r][tx] = src[(long long)(l0+ty+r)*D_ + d0+tx];
    __syncthreads();
    float* dst = vt + (long long)bz * D_ * LK_;
    const int pc = l0 + kperm(tx);
    #pragma unroll
    for (int r = 0; r < 32; r += 8)
        dst[(long long)(d0+ty+r)*LK_ + pc] = tf32r(t[tx][ty+r]);
}

// =================== tf32 mma.sync NT GEMM engine ==========================
// Inputs pre-rounded to tf32 and k-permuted (pairs (k, k+4) adjacent).
// C[m,n] = scale*sum_k A[m,k]*B[n,k] (+ epilogue). Tile 128x256, BK=32,
// 3-stage cp.async, 8 warps (2x4), warp tile 64x64.
// EPI: 0 scale+minmax->f32 | 1 +bias->f32 | 2 +fbw*def->perm-tf32
//      3 relu+bias->perm-tf32 | 4 relu+bias->f32
#define ASTR 40
#define AW (128*ASTR)
#define BW (256*ASTR)
#define STGW (AW+BW)
#define ENG_SMEM (3*STGW*4)

template<int EPI>
__global__ void __launch_bounds__(256, 1)
k6(const float* __restrict__ A, const float* __restrict__ Bm,
   const float* __restrict__ bias, float* __restrict__ C,
   int N, int K, long long sA, long long sB, long long sC, float scale,
   const float* __restrict__ fbw, const float* __restrict__ defv)
{
    extern __shared__ float dsm[];
    __shared__ float red[512];

    const int bz = blockIdx.z;
    A  += (long long)bz * sA;
    Bm += (long long)bz * sB;
    C  += (long long)bz * sC;

    const int m0 = blockIdx.y * 128, n0 = blockIdx.x * 256;
    const int tid = threadIdx.x, lane = tid & 31, warp = tid >> 5;
    const int rbase = (warp & 1) * 64;
    const int cbase = (warp >> 1) * 64;
    const int grp = lane >> 2, qd = lane & 3;

    float* As = dsm;
    float* Bs = dsm + 3*AW;
    const unsigned asu = (unsigned)__cvta_generic_to_shared(As);
    const unsigned bsu = (unsigned)__cvta_generic_to_shared(Bs);

    const int niter = K >> 5;

    auto load_stage = [&](int g){
        const int buf = g % 3;
        const int k0 = g << 5;
        const unsigned ab = asu + buf * (AW*4);
        const unsigned bb = bsu + buf * (BW*4);
        #pragma unroll
        for (int i = 0; i < 4; i++){
            int id = tid + 256*i, row = id >> 3, ch = (id & 7) * 4;
            CPA16(ab + (unsigned)(row*ASTR + ch)*4,
                  A + (long long)(m0 + row)*K + k0 + ch);
        }
        #pragma unroll
        for (int i = 0; i < 8; i++){
            int id = tid + 256*i, row = id >> 3, ch = (id & 7) * 4;
            CPA16(bb + (unsigned)(row*ASTR + ch)*4,
                  Bm + (long long)(n0 + row)*K + k0 + ch);
        }
    };

    float acc[4][8][4];
    #pragma unroll
    for (int mt = 0; mt < 4; mt++)
        #pragma unroll
        for (int u = 0; u < 8; u++)
            #pragma unroll
            for (int r = 0; r < 4; r++) acc[mt][u][r] = 0.f;

    load_stage(0); CPA_COMMIT();
    load_stage(1); CPA_COMMIT();

    for (int it = 0; it < niter; ++it){
        CPA_WAIT1();
        __syncthreads();
        const float* As_s = As + (it % 3)*AW;
        const float* Bs_s = Bs + (it % 3)*BW;
        #pragma unroll
        for (int kk = 0; kk < 32; kk += 8){
            // permuted layout: (k=qd, k=qd+4) adjacent -> one 64-bit LDS
            uint2 aLo[4], aHi[4], bF[8];
            #pragma unroll
            for (int mt = 0; mt < 4; mt++){
                const int m = rbase + mt*16 + grp;
                aLo[mt] = *(const uint2*)&As_s[m*ASTR + kk + 2*qd];
                aHi[mt] = *(const uint2*)&As_s[(m+8)*ASTR + kk + 2*qd];
            }
            #pragma unroll
            for (int u = 0; u < 8; u++){
                const int n = cbase + u*8 + grp;
                bF[u] = *(const uint2*)&Bs_s[n*ASTR + kk + 2*qd];
            }
            #pragma unroll
            for (int mt = 0; mt < 4; mt++)
                #pragma unroll
                for (int u = 0; u < 8; u++)
                    MMA_TF32(acc[mt][u], aLo[mt].x, aHi[mt].x, aLo[mt].y, aHi[mt].y,
                             bF[u].x, bF[u].y);
        }
        __syncthreads();
        if (it + 2 < niter) load_stage(it + 2);
        CPA_COMMIT();
    }

    float lmax = -INFINITY, lmin = INFINITY;
    #pragma unroll
    for (int mt = 0; mt < 4; mt++){
        const int row = m0 + rbase + mt*16 + grp;
        float fw0 = 0.f, fw1 = 0.f;
        if (EPI == 2){ fw0 = fbw[bz*LQ_ + row]; fw1 = fbw[bz*LQ_ + row + 8]; }
        #pragma unroll
        for (int u = 0; u < 8; u++){
            const int col = n0 + cbase + u*8 + qd*2;
            float v0 = acc[mt][u][0], v1 = acc[mt][u][1];
            float v2 = acc[mt][u][2], v3 = acc[mt][u][3];
            if (EPI == 0){
                v0 *= scale; v1 *= scale; v2 *= scale; v3 *= scale;
                lmax = fmaxf(fmaxf(lmax, fmaxf(v0,v1)), fmaxf(v2,v3));
                lmin = fminf(fminf(lmin, fminf(v0,v1)), fminf(v2,v3));
                *(float2*)(C + (long long)row*N + col)     = make_float2(v0, v1);
                *(float2*)(C + (long long)(row+8)*N + col) = make_float2(v2, v3);
            } else if (EPI == 1 || EPI == 4){
                float b0 = bias[col], b1 = bias[col+1];
                v0 += b0; v1 += b1; v2 += b0; v3 += b1;
                if (EPI == 4){
                    v0 = fmaxf(v0,0.f); v1 = fmaxf(v1,0.f);
                    v2 = fmaxf(v2,0.f); v3 = fmaxf(v3,0.f);
                }
                *(float2*)(C + (long long)row*N + col)     = make_float2(v0, v1);
                *(float2*)(C + (long long)(row+8)*N + col) = make_float2(v2, v3);
            } else if (EPI == 2){
                float d0 = defv[bz*D_ + col], d1 = defv[bz*D_ + col + 1];
                const int p0 = n0 + cbase + u*8 + kperm(qd*2);
                const int p1 = n0 + cbase + u*8 + kperm(qd*2 + 1);
                C[(long long)row*N + p0]     = tf32r(v0 + fw0*d0);
                C[(long long)row*N + p1]     = tf32r(v1 + fw0*d1);
                C[(long long)(row+8)*N + p0] = tf32r(v2 + fw1*d0);
                C[(long long)(row+8)*N + p1] = tf32r(v3 + fw1*d1);
            } else { // EPI == 3
                float b0 = bias[col], b1 = bias[col+1];
                const int p0 = n0 + cbase + u*8 + kperm(qd*2);
                const int p1 = n0 + cbase + u*8 + kperm(qd*2 + 1);
                C[(long long)row*N + p0]     = tf32r(fmaxf(v0 + b0, 0.f));
                C[(long long)row*N + p1]     = tf32r(fmaxf(v1 + b1, 0.f));
                C[(long long)(row+8)*N + p0] = tf32r(fmaxf(v2 + b0, 0.f));
                C[(long long)(row+8)*N + p1] = tf32r(fmaxf(v3 + b1, 0.f));
            }
        }
    }
    if (EPI == 0){
        red[tid] = lmax; red[256+tid] = lmin;
        __syncthreads();
        for (int st = 128; st > 0; st >>= 1){
            if (tid < st){
                red[tid]     = fmaxf(red[tid],     red[tid+st]);
                red[256+tid] = fminf(red[256+tid], red[256+tid+st]);
            }
            __syncthreads();
        }
        if (tid == 0){
            atomicMax(&g_umax, fmap(red[0]));
            atomicMin(&g_umin, fmap(red[256]));
        }
    }
}

// ---------------- tiny SIMT GEMM (M=16 paths, raw f32) ---------------------
__global__ void k_small(const float* __restrict__ A, const float* __restrict__ W,
                        const float* __restrict__ bias, float* __restrict__ C,
                        int M, int N, int K, int act)
{
    int g = blockIdx.x*8 + (threadIdx.x>>5), lane = threadIdx.x & 31;
    int m = g / N, n = g % N;
    if (m >= M) return;
    float s = 0.f;
    for (int k = lane; k < K; k += 32) s = fmaf(A[m*K+k], W[n*K+k], s);
    #pragma unroll
    for (int o = 16; o > 0; o >>= 1) s += __shfl_down_sync(0xffffffffu, s, o);
    if (lane == 0){
        s += bias[n];
        if (act) s = fmaxf(s, 0.f);
        C[m*N+n] = s;
    }
}

// ---------------- fallback EMA ---------------------------------------------
__global__ void k_fb(const float* __restrict__ fallback){
    if (threadIdx.x == 0){
        float bmax = funmap(g_umax), bmin = funmap(g_umin);
        g_fb = 0.99f * fallback[0] + 0.01f * ((bmax + bmin) * 0.5f);
    }
}

// ---------------- softmax: f32 scores -> tf32-rounded, permuted weights ----
__global__ void __launch_bounds__(256)
k_softmax(const float* __restrict__ scores, float* __restrict__ wt,
          float* __restrict__ fbw, const void* __restrict__ maskp)
{
    __shared__ float red[256];
    const int row = blockIdx.x, b = row >> 10, tid = threadIdx.x;
    const float* s = scores + (long long)row * LK_;
    const int mode = g_maskmode;
    const float fb = g_fb;

    float4 v = ((const float4*)s)[tid];
    float x[4] = {v.x, v.y, v.z, v.w};
    int mk[4];
    const int base = b*LK_ + tid*4;
    if (mode == 0){
        uchar4 m4 = ((const uchar4*)maskp)[base>>2];
        mk[0]=m4.x!=0; mk[1]=m4.y!=0; mk[2]=m4.z!=0; mk[3]=m4.w!=0;
    } else if (mode == 1){
        int4 m4 = ((const int4*)maskp)[base>>2];
        mk[0]=m4.x!=0; mk[1]=m4.y!=0; mk[2]=m4.z!=0; mk[3]=m4.w!=0;
    } else {
        float4 m4 = ((const float4*)maskp)[base>>2];
        mk[0]=m4.x!=0.f; mk[1]=m4.y!=0.f; mk[2]=m4.z!=0.f; mk[3]=m4.w!=0.f;
    }
    float lmax = fb;
    #pragma unroll
    for (int c = 0; c < 4; c++) if (!mk[c]) lmax = fmaxf(lmax, x[c]);
    red[tid] = lmax; __syncthreads();
    for (int st = 128; st > 0; st >>= 1){
        if (tid < st) red[tid] = fmaxf(red[tid], red[tid+st]);
        __syncthreads();
    }
    const float m = red[0];
    __syncthreads();
    float e[4], lsum = 0.f;
    #pragma unroll
    for (int c = 0; c < 4; c++){ e[c] = mk[c] ? 0.f : expf(x[c]-m); lsum += e[c]; }
    red[tid] = lsum; __syncthreads();
    for (int st = 128; st > 0; st >>= 1){
        if (tid < st) red[tid] += red[tid+st];
        __syncthreads();
    }
    const float fbe = expf(fb - m);
    const float inv = 1.f / (red[0] + fbe);
    // permuted scatter: thread covers cols tid*4..+3 within one 8-group
    long long o = (long long)row*LK_ + (tid>>1)*8 + (tid&1);
    #pragma unroll
    for (int c = 0; c < 4; c++)
        wt[o + 2*c] = tf32r(e[c]*inv);
    if (tid == 0) fbw[row] = fbe * inv;
}

// ---------------- final scorer layer ---------------------------------------
__global__ void k_scorer3(const float* __restrict__ H2, const float* __restrict__ W3,
                          const float* __restrict__ b3, float* __restrict__ out, int M)
{
    int warp = threadIdx.x >> 5, lane = threadIdx.x & 31;
    int row = blockIdx.x * 8 + warp;
    if (row >= M) return;
    const float* h = H2 + (long long)row * (D_/2);
    float sum = 0.f;
    #pragma unroll
    for (int t = 0; t < 8; t++) sum = fmaf(h[lane + t*32], W3[lane + t*32], sum);
    #pragma unroll
    for (int o = 16; o > 0; o >>= 1) sum += __shfl_down_sync(0xffffffffu, sum, o);
    if (lane == 0) out[row] = tanhf(sum + b3[0]);
}

// ---------------------------------------------------------------------------
#define GA(p, sym) { void* _t; cudaGetSymbolAddress(&_t, sym); p = (float*)_t; }

extern "C" void kernel_launch(void* const* d_in, const int* in_sizes, int n_in,
                              void* d_out, int out_size)
{
    const float* uncond_q = (const float*)d_in[0];
    const float* q  = (const float*)d_in[1];
    const float* k  = (const float*)d_in[2];
    const float* v  = (const float*)d_in[3];
    const void*  mask = d_in[4];
    const float* fallback = (const float*)d_in[5];
    const float* Wv = (const float*)d_in[6];
    const float* bv = (const float*)d_in[7];
    const float* Wf = (const float*)d_in[8];
    const float* bf = (const float*)d_in[9];
    const float* W1 = (const float*)d_in[10];
    const float* b1 = (const float*)d_in[11];
    const float* W2 = (const float*)d_in[12];
    const float* b2 = (const float*)d_in[13];
    const float* W3 = (const float*)d_in[14];
    const float* b3 = (const float*)d_in[15];

    float *qp,*kp,*vpin,*wvp,*w1p,*w2p,*vp,*vpt,*scores,*wt,*attn,*h1,*h2;
    float *fbw,*defv,*dh1,*dh2;
    GA(qp,g_qp); GA(kp,g_kp); GA(vpin,g_vpin);
    GA(wvp,g_wvp); GA(w1p,g_w1p); GA(w2p,g_w2p);
    GA(vp,g_vp); GA(vpt,g_vpt); GA(scores,g_scores); GA(wt,g_wt);
    GA(attn,g_attn); GA(h1,g_h1); GA(h2,g_h2);
    GA(fbw,g_fbw); GA(defv,g_def); GA(dh1,g_dh1); GA(dh2,g_dh2);

    cudaFuncSetAttribute(k6<0>, cudaFuncAttributeMaxDynamicSharedMemorySize, ENG_SMEM);
    cudaFuncSetAttribute(k6<1>, cudaFuncAttributeMaxDynamicSharedMemorySize, ENG_SMEM);
    cudaFuncSetAttribute(k6<2>, cudaFuncAttributeMaxDynamicSharedMemorySize, ENG_SMEM);
    cudaFuncSetAttribute(k6<3>, cudaFuncAttributeMaxDynamicSharedMemorySize, ENG_SMEM);
    cudaFuncSetAttribute(k6<4>, cudaFuncAttributeMaxDynamicSharedMemorySize, ENG_SMEM);

    const float inv_sqrt_d = 0.04419417382415922f;
    const long long sQ = (long long)LQ_*D_;
    const long long sS = (long long)LQ_*LK_;
    const long long sVT = (long long)D_*LK_;

    k_init_detect<<<1, 256>>>((const unsigned char*)mask);

    // pre-round + k-permute all GEMM operands
    k_cvtperm<<<8192, 256>>>((const float4*)q,  qp,   NROW_*D_/4);
    k_cvtperm<<<8192, 256>>>((const float4*)k,  kp,   NROW_*D_/4);
    k_cvtperm<<<8192, 256>>>((const float4*)v,  vpin, NROW_*D_/4);
    k_cvtperm<<<256, 256>>>((const float4*)Wv, wvp, D_*D_/4);
    k_cvtperm<<<256, 256>>>((const float4*)W1, w1p, D_*D_/4);
    k_cvtperm<<<128, 256>>>((const float4*)W2, w2p, (D_/2)*D_/4);

    // defaults = uncond_q @ Wf^T + bf (tiny, f32)
    k_small<<<(B_*D_+7)/8, 256>>>(uncond_q, Wf, bf, defv, B_, D_, D_, 0);

    // v_p = V @ Wv^T + bv  -> f32
    k6<1><<<dim3(2,128,1), 256, ENG_SMEM>>>(vpin, wvp, bv, vp,
        D_, D_, 0, 0, 0, 1.f, nullptr, nullptr);

    // scores = Q @ K^T / sqrt(D) + global min/max
    k6<0><<<dim3(4,8,B_), 256, ENG_SMEM>>>(qp, kp, nullptr, scores,
        LK_, D_, sQ, sQ, sS, inv_sqrt_d, nullptr, nullptr);

    k_fb<<<1, 32>>>(fallback);

    // softmax -> rounded+permuted weights + fbw
    k_softmax<<<NROW_, 256>>>(scores, wt, fbw, mask);

    // vp -> [B][D][Lk] transposed, rounded, permuted
    k_trcvt<<<dim3(D_/32, LK_/32, B_), dim3(32,8)>>>(vp, vpt);

    // attn = W @ v_p^T + fbw*defaults -> rounded+permuted
    k6<2><<<dim3(2,8,B_), 256, ENG_SMEM>>>(wt, vpt, nullptr, attn,
        D_, LK_, sS, sVT, sQ, 1.f, fbw, defv);

    // h1 = relu(attn @ W1^T + b1) -> rounded+permuted
    k6<3><<<dim3(2,128,1), 256, ENG_SMEM>>>(attn, w1p, b1, h1,
        D_, D_, 0, 0, 0, 1.f, nullptr, nullptr);

    // h2 = relu(h1 @ W2^T + b2) -> f32
    k6<4><<<dim3(1,128,1), 256, ENG_SMEM>>>(h1, w2p, b2, h2,
        D_/2, D_, 0, 0, 0, 1.f, nullptr, nullptr);

    // defaults scorer (tiny, f32)
    k_small<<<(B_*D_+7)/8, 256>>>(defv, W1, b1, dh1, B_, D_, D_, 1);
    k_small<<<(B_*(D_/2)+7)/8, 256>>>(dh1, W2, b2, dh2, B_, D_/2, D_, 1);

    float* out = (float*)d_out;
    k_scorer3<<<NROW_/8, 256>>>(h2, W3, b3, out, NROW_);
    if (out_size >= NROW_ + B_)
        k_scorer3<<<2, 256>>>(dh2, W3, b3, out + NROW_, B_);
}

// round 7
// speedup vs baseline: 4.0277x; 1.0812x over previous
#include <cuda_runtime.h>
#include <math.h>
#include <stdint.h>

#define D_ 512
#define B_ 16
#define LQ_ 1024
#define LK_ 1024
#define NROW_ (B_*LQ_)

// ---------------- scratch globals (tf32-rounded, k-permuted planes) --------
__device__ __align__(16) float g_qp[NROW_*D_];
__device__ __align__(16) float g_kp[NROW_*D_];
__device__ __align__(16) float g_vpin[NROW_*D_];
__device__ __align__(16) float g_wvp[D_*D_];
__device__ __align__(16) float g_w1p[D_*D_];
__device__ __align__(16) float g_w2p[(D_/2)*D_];
__device__ __align__(16) float g_vpt[B_*D_*LK_];
__device__ __align__(16) float g_scores[(long long)B_*LQ_*LK_];
__device__ __align__(16) float g_wt[(long long)B_*LQ_*LK_];
__device__ __align__(16) float g_attn[NROW_*D_];
__device__ __align__(16) float g_h1[NROW_*D_];
__device__ float g_fbw[NROW_];
__device__ float g_def[B_*D_], g_dh1[B_*D_], g_dh2[B_*(D_/2)];
__device__ unsigned g_umax, g_umin;
__device__ float g_fb;
__device__ int g_maskmode;

// ---------------- helpers ---------------------------------------------------
__device__ __forceinline__ unsigned fmap(float f){
    unsigned u = __float_as_uint(f);
    return (u & 0x80000000u) ? ~u : (u | 0x80000000u);
}
__device__ __forceinline__ float funmap(unsigned m){
    return (m & 0x80000000u) ? __uint_as_float(m ^ 0x80000000u) : __uint_as_float(~m);
}
__device__ __forceinline__ float tf32r(float x){
    unsigned r; asm("cvt.rna.tf32.f32 %0, %1;" : "=r"(r) : "f"(x));
    return __uint_as_float(r);
}
__device__ __forceinline__ int kperm(int c){
    return (c & ~7) | ((c & 3) << 1) | ((c >> 2) & 1);
}
#define CPA16(sa, gp) asm volatile("cp.async.cg.shared.global [%0], [%1], 16;\n" :: "r"(sa), "l"(gp))
#define CPA_COMMIT() asm volatile("cp.async.commit_group;\n" ::: "memory")
#define CPA_WAIT1()  asm volatile("cp.async.wait_group 1;\n" ::: "memory")

#define MMA_TF32(acc, a0, a1, a2, a3, b0, b1) \
    asm volatile( \
        "mma.sync.aligned.m16n8k8.row.col.f32.tf32.tf32.f32 " \
        "{%0,%1,%2,%3}, {%4,%5,%6,%7}, {%8,%9}, {%0,%1,%2,%3};" \
        : "+f"((acc)[0]), "+f"((acc)[1]), "+f"((acc)[2]), "+f"((acc)[3]) \
        : "r"(a0), "r"(a1), "r"(a2), "r"(a3), "r"(b0), "r"(b1))

// ---------------- init + mask dtype detection ------------------------------
__global__ void k_init_detect(const unsigned char* __restrict__ mb){
    __shared__ int sGE2, sOff;
    int tid = threadIdx.x;
    if (tid == 0){ sGE2 = 0; sOff = 0; g_umax = 0u; g_umin = 0xFFFFFFFFu; }
    __syncthreads();
    int ge2 = 0, off = 0;
    for (int i = tid; i < B_*LK_; i += blockDim.x){
        unsigned char c = mb[i];
        if (c > 1) ge2 = 1;
        else if (c == 1 && (i & 3)) off = 1;
    }
    if (ge2) sGE2 = 1;
    if (off) sOff = 1;
    __syncthreads();
    if (tid == 0) g_maskmode = sGE2 ? 2 : (sOff ? 0 : 1);
}

// ---------------- fused converts: f32 -> tf32-rounded, k-permuted ----------
__device__ __forceinline__ void cvt4(const float4* x, float* y, int i){
    float4 v = x[i];
    int base = i * 4;
    y[kperm(base  )] = tf32r(v.x);
    y[kperm(base+1)] = tf32r(v.y);
    y[kperm(base+2)] = tf32r(v.z);
    y[kperm(base+3)] = tf32r(v.w);
}
__global__ void k_cvt3(const float4* __restrict__ x0, float* __restrict__ y0,
                       const float4* __restrict__ x1, float* __restrict__ y1,
                       const float4* __restrict__ x2, float* __restrict__ y2,
                       int n40, int n41, int n42){
    int i = blockIdx.x * blockDim.x + threadIdx.x;
    int z = blockIdx.y;
    if (z == 0){ if (i < n40) cvt4(x0, y0, i); }
    else if (z == 1){ if (i < n41) cvt4(x1, y1, i); }
    else { if (i < n42) cvt4(x2, y2, i); }
}

// =================== tf32 mma.sync NT GEMM engine ==========================
// Inputs pre-rounded to tf32 and k-permuted (pairs (k, k+4) adjacent).
// C[m,n] = scale*sum_k A[m,k]*B[n,k] (+ epilogue). Tile 128x256, BK=32,
// 3-stage cp.async, 8 warps (2x4), warp tile 64x64.
// EPI: 0 scale+minmax->f32 | 2 +fbw*def->perm-tf32 | 3 relu+bias->perm-tf32
//      5 +bias -> vpt transposed+perm-tf32 [B][D][Lk]
//      6 relu+bias -> fused dot(W3)+tanh -> out[row]   (requires gridDim.x==1)
#define ASTR 40
#define AW (128*ASTR)
#define BW (256*ASTR)
#define STGW (AW+BW)
#define ENG_SMEM (3*STGW*4)

template<int EPI>
__global__ void __launch_bounds__(256, 1)
k6(const float* __restrict__ A, const float* __restrict__ Bm,
   const float* __restrict__ bias, float* __restrict__ C,
   int N, int K, long long sA, long long sB, long long sC, float scale,
   const float* __restrict__ fbw, const float* __restrict__ defv)
{
    extern __shared__ float dsm[];
    __shared__ float red[512];

    const int bz = blockIdx.z;
    A  += (long long)bz * sA;
    Bm += (long long)bz * sB;
    C  += (long long)bz * sC;

    const int m0 = blockIdx.y * 128, n0 = blockIdx.x * 256;
    const int tid = threadIdx.x, lane = tid & 31, warp = tid >> 5;
    const int rbase = (warp & 1) * 64;
    const int cbase = (warp >> 1) * 64;
    const int grp = lane >> 2, qd = lane & 3;

    float* As = dsm;
    float* Bs = dsm + 3*AW;
    const unsigned asu = (unsigned)__cvta_generic_to_shared(As);
    const unsigned bsu = (unsigned)__cvta_generic_to_shared(Bs);

    const int niter = K >> 5;

    auto load_stage = [&](int g){
        const int buf = g % 3;
        const int k0 = g << 5;
        const unsigned ab = asu + buf * (AW*4);
        const unsigned bb = bsu + buf * (BW*4);
        #pragma unroll
        for (int i = 0; i < 4; i++){
            int id = tid + 256*i, row = id >> 3, ch = (id & 7) * 4;
            CPA16(ab + (unsigned)(row*ASTR + ch)*4,
                  A + (long long)(m0 + row)*K + k0 + ch);
        }
        #pragma unroll
        for (int i = 0; i < 8; i++){
            int id = tid + 256*i, row = id >> 3, ch = (id & 7) * 4;
            CPA16(bb + (unsigned)(row*ASTR + ch)*4,
                  Bm + (long long)(n0 + row)*K + k0 + ch);
        }
    };

    float acc[4][8][4];
    #pragma unroll
    for (int mt = 0; mt < 4; mt++)
        #pragma unroll
        for (int u = 0; u < 8; u++)
            #pragma unroll
            for (int r = 0; r < 4; r++) acc[mt][u][r] = 0.f;

    load_stage(0); CPA_COMMIT();
    load_stage(1); CPA_COMMIT();

    for (int it = 0; it < niter; ++it){
        CPA_WAIT1();
        __syncthreads();
        const float* As_s = As + (it % 3)*AW;
        const float* Bs_s = Bs + (it % 3)*BW;
        #pragma unroll
        for (int kk = 0; kk < 32; kk += 8){
            uint2 aLo[4], aHi[4], bF[8];
            #pragma unroll
            for (int mt = 0; mt < 4; mt++){
                const int m = rbase + mt*16 + grp;
                aLo[mt] = *(const uint2*)&As_s[m*ASTR + kk + 2*qd];
                aHi[mt] = *(const uint2*)&As_s[(m+8)*ASTR + kk + 2*qd];
            }
            #pragma unroll
            for (int u = 0; u < 8; u++){
                const int n = cbase + u*8 + grp;
                bF[u] = *(const uint2*)&Bs_s[n*ASTR + kk + 2*qd];
            }
            #pragma unroll
            for (int mt = 0; mt < 4; mt++)
                #pragma unroll
                for (int u = 0; u < 8; u++)
                    MMA_TF32(acc[mt][u], aLo[mt].x, aHi[mt].x, aLo[mt].y, aHi[mt].y,
                             bF[u].x, bF[u].y);
        }
        __syncthreads();
        if (it + 2 < niter) load_stage(it + 2);
        CPA_COMMIT();
    }

    if (EPI == 0){
        float lmax = -INFINITY, lmin = INFINITY;
        #pragma unroll
        for (int mt = 0; mt < 4; mt++){
            const int row = m0 + rbase + mt*16 + grp;
            #pragma unroll
            for (int u = 0; u < 8; u++){
                const int col = n0 + cbase + u*8 + qd*2;
                float v0 = acc[mt][u][0]*scale, v1 = acc[mt][u][1]*scale;
                float v2 = acc[mt][u][2]*scale, v3 = acc[mt][u][3]*scale;
                lmax = fmaxf(fmaxf(lmax, fmaxf(v0,v1)), fmaxf(v2,v3));
                lmin = fminf(fminf(lmin, fminf(v0,v1)), fminf(v2,v3));
                *(float2*)(C + (long long)row*N + col)     = make_float2(v0, v1);
                *(float2*)(C + (long long)(row+8)*N + col) = make_float2(v2, v3);
            }
        }
        red[tid] = lmax; red[256+tid] = lmin;
        __syncthreads();
        for (int st = 128; st > 0; st >>= 1){
            if (tid < st){
                red[tid]     = fmaxf(red[tid],     red[tid+st]);
                red[256+tid] = fminf(red[256+tid], red[256+tid+st]);
            }
            __syncthreads();
        }
        if (tid == 0){
            atomicMax(&g_umax, fmap(red[0]));
            atomicMin(&g_umin, fmap(red[256]));
        }
    } else if (EPI == 2 || EPI == 3){
        #pragma unroll
        for (int mt = 0; mt < 4; mt++){
            const int row = m0 + rbase + mt*16 + grp;
            float fw0 = 0.f, fw1 = 0.f;
            if (EPI == 2){ fw0 = fbw[bz*LQ_ + row]; fw1 = fbw[bz*LQ_ + row + 8]; }
            #pragma unroll
            for (int u = 0; u < 8; u++){
                const int col = n0 + cbase + u*8 + qd*2;
                float v0 = acc[mt][u][0], v1 = acc[mt][u][1];
                float v2 = acc[mt][u][2], v3 = acc[mt][u][3];
                const int p0 = n0 + cbase + u*8 + kperm(qd*2);
                const int p1 = n0 + cbase + u*8 + kperm(qd*2 + 1);
                if (EPI == 2){
                    float d0 = defv[bz*D_ + col], d1 = defv[bz*D_ + col + 1];
                    C[(long long)row*N + p0]     = tf32r(v0 + fw0*d0);
                    C[(long long)row*N + p1]     = tf32r(v1 + fw0*d1);
                    C[(long long)(row+8)*N + p0] = tf32r(v2 + fw1*d0);
                    C[(long long)(row+8)*N + p1] = tf32r(v3 + fw1*d1);
                } else {
                    float b0 = bias[col], b1 = bias[col+1];
                    C[(long long)row*N + p0]     = tf32r(fmaxf(v0 + b0, 0.f));
                    C[(long long)row*N + p1]     = tf32r(fmaxf(v1 + b1, 0.f));
                    C[(long long)(row+8)*N + p0] = tf32r(fmaxf(v2 + b0, 0.f));
                    C[(long long)(row+8)*N + p1] = tf32r(fmaxf(v3 + b1, 0.f));
                }
            }
        }
    } else if (EPI == 5){
        // vp epilogue: C = vpt base; write [B][D][Lk] transposed + permuted
        #pragma unroll
        for (int mt = 0; mt < 4; mt++){
            const int r0 = m0 + rbase + mt*16 + grp;
            const int r1 = r0 + 8;
            const int b0i = r0 >> 10, l0i = r0 & 1023;
            const int b1i = r1 >> 10, l1i = r1 & 1023;
            const long long o0 = (long long)b0i*D_*LK_ + kperm(l0i);
            const long long o1 = (long long)b1i*D_*LK_ + kperm(l1i);
            #pragma unroll
            for (int u = 0; u < 8; u++){
                const int col = n0 + cbase + u*8 + qd*2;
                const float bb0 = bias[col], bb1 = bias[col+1];
                C[o0 + (long long)col*LK_]     = tf32r(acc[mt][u][0] + bb0);
                C[o0 + (long long)(col+1)*LK_] = tf32r(acc[mt][u][1] + bb1);
                C[o1 + (long long)col*LK_]     = tf32r(acc[mt][u][2] + bb0);
                C[o1 + (long long)(col+1)*LK_] = tf32r(acc[mt][u][3] + bb1);
            }
        }
    } else if (EPI == 6){
        // fused final scorer: relu(acc+bias) dot W3(=fbw) + b3(=defv[0]) -> tanh -> C[row]
        float part[8];
        #pragma unroll
        for (int i = 0; i < 8; i++) part[i] = 0.f;
        #pragma unroll
        for (int u = 0; u < 8; u++){
            const int col = cbase + u*8 + qd*2;
            const float w0 = fbw[col], w1 = fbw[col+1];
            const float b0 = bias[col], b1 = bias[col+1];
            #pragma unroll
            for (int mt = 0; mt < 4; mt++){
                part[mt*2]   += fmaxf(acc[mt][u][0]+b0, 0.f)*w0 + fmaxf(acc[mt][u][1]+b1, 0.f)*w1;
                part[mt*2+1] += fmaxf(acc[mt][u][2]+b0, 0.f)*w0 + fmaxf(acc[mt][u][3]+b1, 0.f)*w1;
            }
        }
        #pragma unroll
        for (int i = 0; i < 8; i++){
            part[i] += __shfl_xor_sync(0xffffffffu, part[i], 1);
            part[i] += __shfl_xor_sync(0xffffffffu, part[i], 2);
        }
        if (qd == 0){
            const int cg = warp >> 1;
            #pragma unroll
            for (int mt = 0; mt < 4; mt++){
                red[(rbase + mt*16 + grp)*4 + cg]     = part[mt*2];
                red[(rbase + mt*16 + grp + 8)*4 + cg] = part[mt*2+1];
            }
        }
        __syncthreads();
        if (tid < 128){
            float s = red[tid*4] + red[tid*4+1] + red[tid*4+2] + red[tid*4+3];
            C[m0 + tid] = tanhf(s + defv[0]);
        }
    }
}

// ---------------- tiny SIMT GEMM (M=16 paths, raw f32) ---------------------
__global__ void k_small(const float* __restrict__ A, const float* __restrict__ W,
                        const float* __restrict__ bias, float* __restrict__ C,
                        int M, int N, int K, int act)
{
    int g = blockIdx.x*8 + (threadIdx.x>>5), lane = threadIdx.x & 31;
    int m = g / N, n = g % N;
    if (m >= M) return;
    float s = 0.f;
    for (int k = lane; k < K; k += 32) s = fmaf(A[m*K+k], W[n*K+k], s);
    #pragma unroll
    for (int o = 16; o > 0; o >>= 1) s += __shfl_down_sync(0xffffffffu, s, o);
    if (lane == 0){
        s += bias[n];
        if (act) s = fmaxf(s, 0.f);
        C[m*N+n] = s;
    }
}

// ---------------- fallback EMA ---------------------------------------------
__global__ void k_fb(const float* __restrict__ fallback){
    if (threadIdx.x == 0){
        float bmax = funmap(g_umax), bmin = funmap(g_umin);
        g_fb = 0.99f * fallback[0] + 0.01f * ((bmax + bmin) * 0.5f);
    }
}

// ---------------- softmax: group-coalesced, 128 thr/row --------------------
__global__ void __launch_bounds__(128)
k_softmax(const float* __restrict__ scores, float* __restrict__ wt,
          float* __restrict__ fbw, const void* __restrict__ maskp)
{
    __shared__ float red[128];
    const int row = blockIdx.x, b = row >> 10, g = threadIdx.x;  // g = 8-col group
    const float* s = scores + (long long)row * LK_ + g*8;
    const int mode = g_maskmode;
    const float fb = g_fb;

    float4 va = ((const float4*)s)[0];
    float4 vb = ((const float4*)s)[1];
    float x[8] = {va.x,va.y,va.z,va.w, vb.x,vb.y,vb.z,vb.w};
    int mk[8];
    const int mbase = b*LK_ + g*8;
    if (mode == 0){
        uchar4 a = ((const uchar4*)maskp)[(mbase>>2)];
        uchar4 c = ((const uchar4*)maskp)[(mbase>>2)+1];
        mk[0]=a.x!=0; mk[1]=a.y!=0; mk[2]=a.z!=0; mk[3]=a.w!=0;
        mk[4]=c.x!=0; mk[5]=c.y!=0; mk[6]=c.z!=0; mk[7]=c.w!=0;
    } else if (mode == 1){
        int4 a = ((const int4*)maskp)[(mbase>>2)];
        int4 c = ((const int4*)maskp)[(mbase>>2)+1];
        mk[0]=a.x!=0; mk[1]=a.y!=0; mk[2]=a.z!=0; mk[3]=a.w!=0;
        mk[4]=c.x!=0; mk[5]=c.y!=0; mk[6]=c.z!=0; mk[7]=c.w!=0;
    } else {
        float4 a = ((const float4*)maskp)[(mbase>>2)];
        float4 c = ((const float4*)maskp)[(mbase>>2)+1];
        mk[0]=a.x!=0.f; mk[1]=a.y!=0.f; mk[2]=a.z!=0.f; mk[3]=a.w!=0.f;
        mk[4]=c.x!=0.f; mk[5]=c.y!=0.f; mk[6]=c.z!=0.f; mk[7]=c.w!=0.f;
    }
    float lmax = fb;
    #pragma unroll
    for (int c = 0; c < 8; c++) if (!mk[c]) lmax = fmaxf(lmax, x[c]);
    red[g] = lmax; __syncthreads();
    for (int st = 64; st > 0; st >>= 1){
        if (g < st) red[g] = fmaxf(red[g], red[g+st]);
        __syncthreads();
    }
    const float m = red[0];
    __syncthreads();
    float e[8], lsum = 0.f;
    #pragma unroll
    for (int c = 0; c < 8; c++){ e[c] = mk[c] ? 0.f : expf(x[c]-m); lsum += e[c]; }
    red[g] = lsum; __syncthreads();
    for (int st = 64; st > 0; st >>= 1){
        if (g < st) red[g] += red[g+st];
        __syncthreads();
    }
    const float fbe = expf(fb - m);
    const float inv = 1.f / (red[0] + fbe);
    // permuted within 8-group: dest = {e0,e4,e1,e5, e2,e6,e3,e7} * inv
    float* w = wt + (long long)row*LK_ + g*8;
    ((float4*)w)[0] = make_float4(tf32r(e[0]*inv), tf32r(e[4]*inv), tf32r(e[1]*inv), tf32r(e[5]*inv));
    ((float4*)w)[1] = make_float4(tf32r(e[2]*inv), tf32r(e[6]*inv), tf32r(e[3]*inv), tf32r(e[7]*inv));
    if (g == 0) fbw[row] = fbe * inv;
}

// ---------------- scorer3 (defaults path only, 16 rows) --------------------
__global__ void k_scorer3(const float* __restrict__ H2, const float* __restrict__ W3,
                          const float* __restrict__ b3, float* __restrict__ out, int M)
{
    int warp = threadIdx.x >> 5, lane = threadIdx.x & 31;
    int row = blockIdx.x * 8 + warp;
    if (row >= M) return;
    const float* h = H2 + (long long)row * (D_/2);
    float sum = 0.f;
    #pragma unroll
    for (int t = 0; t < 8; t++) sum = fmaf(h[lane + t*32], W3[lane + t*32], sum);
    #pragma unroll
    for (int o = 16; o > 0; o >>= 1) sum += __shfl_down_sync(0xffffffffu, sum, o);
    if (lane == 0) out[row] = tanhf(sum + b3[0]);
}

// ---------------------------------------------------------------------------
#define GA(p, sym) { void* _t; cudaGetSymbolAddress(&_t, sym); p = (float*)_t; }

extern "C" void kernel_launch(void* const* d_in, const int* in_sizes, int n_in,
                              void* d_out, int out_size)
{
    const float* uncond_q = (const float*)d_in[0];
    const float* q  = (const float*)d_in[1];
    const float* k  = (const float*)d_in[2];
    const float* v  = (const float*)d_in[3];
    const void*  mask = d_in[4];
    const float* fallback = (const float*)d_in[5];
    const float* Wv = (const float*)d_in[6];
    const float* bv = (const float*)d_in[7];
    const float* Wf = (const float*)d_in[8];
    const float* bf = (const float*)d_in[9];
    const float* W1 = (const float*)d_in[10];
    const float* b1 = (const float*)d_in[11];
    const float* W2 = (const float*)d_in[12];
    const float* b2 = (const float*)d_in[13];
    const float* W3 = (const float*)d_in[14];
    const float* b3 = (const float*)d_in[15];

    float *qp,*kp,*vpin,*wvp,*w1p,*w2p,*vpt,*scores,*wt,*attn,*h1;
    float *fbw,*defv,*dh1,*dh2;
    GA(qp,g_qp); GA(kp,g_kp); GA(vpin,g_vpin);
    GA(wvp,g_wvp); GA(w1p,g_w1p); GA(w2p,g_w2p);
    GA(vpt,g_vpt); GA(scores,g_scores); GA(wt,g_wt);
    GA(attn,g_attn); GA(h1,g_h1);
    GA(fbw,g_fbw); GA(defv,g_def); GA(dh1,g_dh1); GA(dh2,g_dh2);

    cudaFuncSetAttribute(k6<0>, cudaFuncAttributeMaxDynamicSharedMemorySize, ENG_SMEM);
    cudaFuncSetAttribute(k6<2>, cudaFuncAttributeMaxDynamicSharedMemorySize, ENG_SMEM);
    cudaFuncSetAttribute(k6<3>, cudaFuncAttributeMaxDynamicSharedMemorySize, ENG_SMEM);
    cudaFuncSetAttribute(k6<5>, cudaFuncAttributeMaxDynamicSharedMemorySize, ENG_SMEM);
    cudaFuncSetAttribute(k6<6>, cudaFuncAttributeMaxDynamicSharedMemorySize, ENG_SMEM);

    const float inv_sqrt_d = 0.04419417382415922f;
    const long long sQ = (long long)LQ_*D_;
    const long long sS = (long long)LQ_*LK_;
    const long long sVT = (long long)D_*LK_;

    k_init_detect<<<1, 256>>>((const unsigned char*)mask);

    // pre-round + k-permute inputs (fused) and weights (fused)
    k_cvt3<<<dim3(8192,3), 256>>>((const float4*)q, qp, (const float4*)k, kp,
                                  (const float4*)v, vpin,
                                  NROW_*D_/4, NROW_*D_/4, NROW_*D_/4);
    k_cvt3<<<dim3(256,3), 256>>>((const float4*)Wv, wvp, (const float4*)W1, w1p,
                                 (const float4*)W2, w2p,
                                 D_*D_/4, D_*D_/4, (D_/2)*D_/4);

    // defaults = uncond_q @ Wf^T + bf (tiny, f32)
    k_small<<<(B_*D_+7)/8, 256>>>(uncond_q, Wf, bf, defv, B_, D_, D_, 0);

    // v_p = V @ Wv^T + bv -> vpt [B][D][Lk] transposed+permuted (fused)
    k6<5><<<dim3(2,128,1), 256, ENG_SMEM>>>(vpin, wvp, bv, vpt,
        D_, D_, 0, 0, 0, 1.f, nullptr, nullptr);

    // scores = Q @ K^T / sqrt(D) + global min/max
    k6<0><<<dim3(4,8,B_), 256, ENG_SMEM>>>(qp, kp, nullptr, scores,
        LK_, D_, sQ, sQ, sS, inv_sqrt_d, nullptr, nullptr);

    k_fb<<<1, 32>>>(fallback);

    // softmax -> rounded+permuted weights + fbw
    k_softmax<<<NROW_, 128>>>(scores, wt, fbw, mask);

    // attn = W @ v_p^T + fbw*defaults -> rounded+permuted
    k6<2><<<dim3(2,8,B_), 256, ENG_SMEM>>>(wt, vpt, nullptr, attn,
        D_, LK_, sS, sVT, sQ, 1.f, fbw, defv);

    // h1 = relu(attn @ W1^T + b1) -> rounded+permuted
    k6<3><<<dim3(2,128,1), 256, ENG_SMEM>>>(attn, w1p, b1, h1,
        D_, D_, 0, 0, 0, 1.f, nullptr, nullptr);

    // fused: h2 = relu(h1 @ W2^T + b2); out = tanh(h2 . W3 + b3)
    float* out = (float*)d_out;
    k6<6><<<dim3(1,128,1), 256, ENG_SMEM>>>(h1, w2p, b2, out,
        D_/2, D_, 0, 0, 0, 1.f, W3, b3);

    // defaults scorer (tiny, f32)
    k_small<<<(B_*D_+7)/8, 256>>>(defv, W1, b1, dh1, B_, D_, D_, 1);
    k_small<<<(B_*(D_/2)+7)/8, 256>>>(dh1, W2, b2, dh2, B_, D_/2, D_, 1);
    if (out_size >= NROW_ + B_)
        k_scorer3<<<2, 256>>>(dh2, W3, b3, out + NROW_, B_);
}